// round 10
// baseline (speedup 1.0000x reference)
#include <cuda_runtime.h>
#include <stdint.h>
#include <math.h>

#define BATCH 256
#define NT_OUT 32768
#define OUT_ELEMS (32u * 3u * 32768u * 8u)   // 25,165,824

// scratch — __device__ globals, no allocs
__device__ float g_bufA[BATCH * 64 * 2048];
__device__ float g_bufB[BATCH * 64 * 2048];
__device__ float g_wprep[131072];
__device__ double g_loss_accum;
__device__ int    g_mask[BATCH];

typedef unsigned long long u64;

__device__ __forceinline__ void fma2(u64 &d, u64 a, u64 b) {
    asm("fma.rn.f32x2 %0, %1, %2, %0;" : "+l"(d) : "l"(a), "l"(b));
}
__device__ __forceinline__ u64 pack2(float lo, float hi) {
    u64 r; asm("mov.b64 %0, {%1, %2};" : "=l"(r) : "f"(lo), "f"(hi)); return r;
}
__device__ __forceinline__ void unpack2(u64 v, float &lo, float &hi) {
    asm("mov.b64 {%0, %1}, %2;" : "=f"(lo), "=f"(hi) : "l"(v));
}
__device__ __forceinline__ unsigned sm_u32(const void* p) {
    unsigned a;
    asm("{.reg .u64 t; cvta.to.shared.u64 t, %1; cvt.u32.u64 %0, t;}"
        : "=r"(a) : "l"(p));
    return a;
}

// ---------------------------------------------------------------------------
// One prep kernel: all 5 layers' dup-pair weight reformat + accum/mask init.
// blockIdx.y = layer (0..4), 5 = init.
// ---------------------------------------------------------------------------
__global__ void prep_all(const float* __restrict__ w0, const float* __restrict__ w1,
                         const float* __restrict__ w2, const float* __restrict__ w3,
                         const float* __restrict__ w4, float* __restrict__ wprep,
                         double* accum, int* mask)
{
    const int layer = blockIdx.y;
    if (layer == 5) {
        if (blockIdx.x == 0) {
            int t = threadIdx.x;
            if (t == 0) *accum = 0.0;
            if (t < BATCH) mask[t] = 0;
        }
        return;
    }
    const int CINs[5]   = {128, 64, 32, 16, 8};
    const int COUTs[5]  = {64, 32, 16, 8, 3};
    const int COUTPs[5] = {64, 32, 16, 8, 4};
    const int OFFs[5]   = {0, 81920, 102400, 107520, 108800};
    const float* W[5]   = {w0, w1, w2, w3, w4};
    const int CIN = CINs[layer], COUT = COUTs[layer], COUTP = COUTPs[layer];
    const int CHUNK = 8;
    const float* w = W[layer];
    float* dst = wprep + OFFs[layer];

    int n = COUT * CIN * 5;
    for (int idx = blockIdx.x * 256 + threadIdx.x; idx < n; idx += gridDim.x * 256) {
        int co = idx / (CIN * 5), r = idx - co * (CIN * 5);
        int ci = r / 5, k = r - ci * 5;
        int q = ci / CHUNK, cil = ci - q * CHUNK;
        float v = w[idx];
        int o = q * (CHUNK * 10 * COUTP) + (cil * 5 + k) * 2 * COUTP + 2 * co;
        dst[o] = v; dst[o + 1] = v;
    }
}

// ---------------------------------------------------------------------------
// Fused conv(dilated, reflect) + BN/bias + ReLU + linear x2 upsample.
// cp.async double-buffered staging; f32x2 FMA; smem W broadcast;
// shuffle-based upsample epilogue. MAXB = CTAs/SM hint.
// ---------------------------------------------------------------------------
template<int CIN, int COUT, int DIL, int TL, int RC, int CHUNK, bool BN, bool FINAL,
         int MAXB>
__global__ __launch_bounds__(256, MAXB)
void conv_layer(const float* __restrict__ x,   // [B, CIN, L]
                const float* __restrict__ wp,  // prepped weights
                const float* __restrict__ gg,
                const float* __restrict__ bb,
                const float* __restrict__ mm,
                const float* __restrict__ vv,
                const float* __restrict__ bout,
                float* __restrict__ y,          // [B, COUT, 2L]
                int L)
{
    constexpr int PAD   = 2 * DIL;
    constexpr int SFT   = PAD + 4;
    constexpr int HALO  = TL + 2 * PAD + 5;
    constexpr int HALOP = (HALO + 3) & ~3;
    constexpr int NPG   = TL / 4;
    constexpr int COUTP = (COUT + 3) & ~3;
    constexpr int NQ    = (RC + 1) / 2;
    constexpr int WCH   = CHUNK * 10 * COUTP;
    constexpr int NCH   = CIN / CHUNK;
    constexpr int WPC   = NPG / 32;             // warps per cout-group

    const int tid  = threadIdx.x;
    const int tile = blockIdx.x;
    const int b    = blockIdx.y;
    const int pg   = tid % NPG;
    const int cg   = tid / NPG;
    const int lane = tid & 31;
    const int wic  = pg >> 5;
    const int lb   = pg * 4;
    const int cb   = cg * RC;

    extern __shared__ float sm[];
    float* Xbuf[2] = { sm, sm + CHUNK * HALOP };
    float* Wbuf[2] = { sm + 2 * CHUNK * HALOP, sm + 2 * CHUNK * HALOP + WCH };
    float* YsE   = sm + 2 * CHUNK * HALOP + 2 * WCH;   // [COUT][2]
    float* BndA3 = YsE + 2 * COUT;                     // [COUT][WPC]
    float* BndA0 = BndA3 + COUT * WPC;                 // [COUT][WPC]

    const float* xb    = x + (size_t)b * CIN * L;
    const int    gbase = tile * TL - SFT;

    u64 acc[RC][2];
#pragma unroll
    for (int q = 0; q < RC; q++) { acc[q][0] = 0ull; acc[q][1] = 0ull; }

    float eacc = 0.f;
    const int eIdx = tid >> 1, eSide = tid & 1;
    int ej = 0;
    if (tid < 2 * COUT) {
        int gl = tile * TL + (eSide ? TL : -1);
        if (gl < 0)  gl = 0;
        if (gl >= L) gl = L - 1;
        ej = gl - tile * TL;
    }

    auto stage = [&](int p, int cc) {
        float* Xd = Xbuf[p];
        for (int idx = tid; idx < CHUNK * HALO; idx += 256) {
            int ci = idx / HALO, j = idx - ci * HALO;
            int gi = gbase + j;
            if (gi < 0)  gi = -gi;
            if (gi >= L) gi = 2 * L - 2 - gi;
            unsigned d = sm_u32(Xd + ci * HALOP + j);
            const float* s = xb + (size_t)(cc * CHUNK + ci) * L + gi;
            asm volatile("cp.async.ca.shared.global [%0], [%1], 4;" :: "r"(d), "l"(s));
        }
        const float4* wsrc = (const float4*)(wp + (size_t)cc * WCH);
        float* Wd = Wbuf[p];
        for (int idx = tid; idx < WCH / 4; idx += 256) {
            unsigned d = sm_u32(Wd + idx * 4);
            asm volatile("cp.async.cg.shared.global [%0], [%1], 16;"
                         :: "r"(d), "l"(wsrc + idx));
        }
        asm volatile("cp.async.commit_group;");
    };

    stage(0, 0);

    for (int cc = 0; cc < NCH; cc++) {
        const int p = cc & 1;
        asm volatile("cp.async.wait_group 0;");
        __syncthreads();
        if (cc + 1 < NCH) stage(p ^ 1, cc + 1);

        const float* Xs = Xbuf[p];
        const float* Ws = Wbuf[p];

#pragma unroll 2
        for (int ci = 0; ci < CHUNK; ci++) {
            const float* xr = Xs + ci * HALOP + lb + 4;
            if (DIL == 1) {
                float4 f0 = *(const float4*)xr;
                float4 f1 = *(const float4*)(xr + 4);
                float fv[8] = {f0.x, f0.y, f0.z, f0.w, f1.x, f1.y, f1.z, f1.w};
                u64 P[7];
#pragma unroll
                for (int i = 0; i < 7; i++) P[i] = pack2(fv[i], fv[i + 1]);
#pragma unroll
                for (int k = 0; k < 5; k++) {
                    u64 xp0 = P[k], xp1 = P[k + 2];
                    const float* wr = Ws + (ci * 5 + k) * 2 * COUTP + 2 * cb;
#pragma unroll
                    for (int qq = 0; qq < NQ; qq++) {
                        ulonglong2 wv = *(const ulonglong2*)(wr + 4 * qq);
                        fma2(acc[2 * qq][0], wv.x, xp0);
                        fma2(acc[2 * qq][1], wv.x, xp1);
                        if (2 * qq + 1 < RC) {
                            fma2(acc[2 * qq + 1][0], wv.y, xp0);
                            fma2(acc[2 * qq + 1][1], wv.y, xp1);
                        }
                    }
                }
            } else if (DIL == 2) {
                ulonglong2 e0 = *(const ulonglong2*)xr;
                ulonglong2 e1 = *(const ulonglong2*)(xr + 4);
                ulonglong2 e2 = *(const ulonglong2*)(xr + 8);
                u64 E[6] = {e0.x, e0.y, e1.x, e1.y, e2.x, e2.y};
#pragma unroll
                for (int k = 0; k < 5; k++) {
                    u64 xp0 = E[k], xp1 = E[k + 1];
                    const float* wr = Ws + (ci * 5 + k) * 2 * COUTP + 2 * cb;
#pragma unroll
                    for (int qq = 0; qq < NQ; qq++) {
                        ulonglong2 wv = *(const ulonglong2*)(wr + 4 * qq);
                        fma2(acc[2 * qq][0], wv.x, xp0);
                        fma2(acc[2 * qq][1], wv.x, xp1);
                        if (2 * qq + 1 < RC) {
                            fma2(acc[2 * qq + 1][0], wv.y, xp0);
                            fma2(acc[2 * qq + 1][1], wv.y, xp1);
                        }
                    }
                }
            } else {
#pragma unroll
                for (int k = 0; k < 5; k++) {
                    ulonglong2 xv = *(const ulonglong2*)(xr + k * DIL);
                    u64 xp0 = xv.x, xp1 = xv.y;
                    const float* wr = Ws + (ci * 5 + k) * 2 * COUTP + 2 * cb;
#pragma unroll
                    for (int qq = 0; qq < NQ; qq++) {
                        ulonglong2 wv = *(const ulonglong2*)(wr + 4 * qq);
                        fma2(acc[2 * qq][0], wv.x, xp0);
                        fma2(acc[2 * qq][1], wv.x, xp1);
                        if (2 * qq + 1 < RC) {
                            fma2(acc[2 * qq + 1][0], wv.y, xp0);
                            fma2(acc[2 * qq + 1][1], wv.y, xp1);
                        }
                    }
                }
            }
        }

        if (tid < 2 * COUT) {
#pragma unroll 1
            for (int ci = 0; ci < CHUNK; ci++)
#pragma unroll
                for (int k = 0; k < 5; k++)
                    eacc = fmaf(Ws[(ci * 5 + k) * 2 * COUTP + 2 * eIdx],
                                Xs[ci * HALOP + ej + 4 + k * DIL], eacc);
        }
    }

    // ---- BN/bias (+ReLU) into registers; publish warp-boundary values ----
    float v[RC][4];
#pragma unroll
    for (int q = 0; q < RC; q++) {
        int c = cb + q;
        float sc, sh;
        if (FINAL) { sc = 1.f; sh = bout[c]; }
        else {
            float inv = gg[c] * rsqrtf(vv[c] + 1e-5f);
            sc = inv; sh = bb[c] - mm[c] * inv;
        }
        float a0, a1, a2, a3;
        unpack2(acc[q][0], a0, a1);
        unpack2(acc[q][1], a2, a3);
        a0 = a0 * sc + sh; a1 = a1 * sc + sh;
        a2 = a2 * sc + sh; a3 = a3 * sc + sh;
        if (BN) {
            a0 = fmaxf(a0, 0.f); a1 = fmaxf(a1, 0.f);
            a2 = fmaxf(a2, 0.f); a3 = fmaxf(a3, 0.f);
        }
        v[q][0] = a0; v[q][1] = a1; v[q][2] = a2; v[q][3] = a3;
        if (lane == 31) BndA3[c * WPC + wic] = a3;
        if (lane == 0)  BndA0[c * WPC + wic] = a0;
    }
    if (tid < 2 * COUT) {
        int c = eIdx;
        float sc, sh;
        if (FINAL) { sc = 1.f; sh = bout[c]; }
        else {
            float inv = gg[c] * rsqrtf(vv[c] + 1e-5f);
            sc = inv; sh = bb[c] - mm[c] * inv;
        }
        float val = eacc * sc + sh;
        if (BN) val = fmaxf(val, 0.f);
        YsE[2 * c + eSide] = val;
    }
    __syncthreads();

    // ---- shuffle-based x2 upsample + coalesced store ----
    const int Lup = 2 * L;
#pragma unroll
    for (int q = 0; q < RC; q++) {
        int c = cb + q;
        float yl = __shfl_up_sync(0xffffffffu, v[q][3], 1);
        float yr = __shfl_down_sync(0xffffffffu, v[q][0], 1);
        if (lane == 0)  yl = (wic == 0)       ? YsE[2 * c]     : BndA3[c * WPC + wic - 1];
        if (lane == 31) yr = (wic == WPC - 1) ? YsE[2 * c + 1] : BndA0[c * WPC + wic + 1];
        float y0 = v[q][0], y1 = v[q][1], y2 = v[q][2], y3 = v[q][3];
        float o0 = 0.25f * yl + 0.75f * y0, o1 = 0.75f * y0 + 0.25f * y1;
        float o2 = 0.25f * y0 + 0.75f * y1, o3 = 0.75f * y1 + 0.25f * y2;
        float o4 = 0.25f * y1 + 0.75f * y2, o5 = 0.75f * y2 + 0.25f * y3;
        float o6 = 0.25f * y2 + 0.75f * y3, o7 = 0.75f * y3 + 0.25f * yr;
        size_t off = ((size_t)b * COUT + c) * Lup + 2 * (tile * TL + lb);
        *(float4*)(y + off)     = make_float4(o0, o1, o2, o3);
        *(float4*)(y + off + 4) = make_float4(o4, o5, o6, o7);
    }
}

// ---------------------------------------------------------------------------
// Transpose [b=bt*8+st][3][T] -> [bt][3][T][st] + fused masked CE loss.
// ---------------------------------------------------------------------------
#define TT 512
#define TTP 516
__global__ __launch_bounds__(256)
void transpose_loss(const float* __restrict__ in, const float* __restrict__ tg,
                    float* __restrict__ out, double* accum, int* mask)
{
    const int bt = blockIdx.y;
    const int t0 = blockIdx.x * TT;
    const int tid = threadIdx.x;
    extern __shared__ float tile[];               // [3][8][TTP]

    for (int idx = tid; idx < 3 * 8 * TT; idx += 256) {
        int c = idx / (8 * TT), r = idx - c * (8 * TT);
        int st = r / TT, t = r - st * TT;
        tile[(c * 8 + st) * TTP + t] =
            in[((size_t)(bt * 8 + st) * 3 + c) * NT_OUT + t0 + t];
    }
    __syncthreads();

    float s = 0.f;
    bool nz = false;
    const size_t ob = ((size_t)bt * 3) * NT_OUT * 8 + (size_t)t0 * 8;
    const size_t cs = (size_t)NT_OUT * 8;
#pragma unroll 4
    for (int i = 0; i < (TT * 8) / 256; i++) {
        int f = i * 256 + tid;
        int t = f >> 3, st = f & 7;
        float o0 = tile[(0 * 8 + st) * TTP + t];
        float o1 = tile[(1 * 8 + st) * TTP + t];
        float o2 = tile[(2 * 8 + st) * TTP + t];
        out[ob + f]          = o0;
        out[ob + cs + f]     = o1;
        out[ob + 2 * cs + f] = o2;
        float t0v = tg[ob + f], t1v = tg[ob + cs + f], t2v = tg[ob + 2 * cs + f];
        float mx  = fmaxf(o0, fmaxf(o1, o2));
        float lse = mx + __logf(__expf(o0 - mx) + __expf(o1 - mx) + __expf(o2 - mx));
        s += t0v * (lse - o0) + t1v * (lse - o1) + t2v * (lse - o2);
        nz = nz || (t0v != 0.f) || (t1v != 0.f) || (t2v != 0.f);
    }
    if (nz) atomicOr(&mask[bt * 8 + (tid & 7)], 1);

    __shared__ float red[256];
    red[tid] = s;
    __syncthreads();
    for (int o = 128; o > 0; o >>= 1) {
        if (tid < o) red[tid] += red[tid + o];
        __syncthreads();
    }
    if (tid == 0) atomicAdd(accum, (double)red[0]);
}

__global__ void finalize_kernel(const double* accum, const int* mask,
                                float* out, int out_size)
{
    if (threadIdx.x != 0 || blockIdx.x != 0) return;
    int num = 0;
    for (int i = 0; i < BATCH; i++) num += (mask[i] ? 1 : 0);
    double loss = *accum / ((double)num * (double)NT_OUT);
    if ((unsigned)out_size > OUT_ELEMS) out[OUT_ELEMS] = (float)loss;
}

// ---------------------------------------------------------------------------
static constexpr int conv_smem(int CIN, int COUT, int DIL, int TL, int CHUNK) {
    int halop = ((TL + 4 * DIL + 5) + 3) & ~3;
    int coutp = (COUT + 3) & ~3;
    int wpc = (TL / 4) / 32;
    return (2 * CHUNK * halop + 2 * CHUNK * 10 * coutp + 2 * COUT + 2 * COUT * wpc) * 4;
}

extern "C" void kernel_launch(void* const* d_in, const int* in_sizes, int n_in,
                              void* d_out, int out_size)
{
    const float* x  = (const float*)d_in[0];
    const float* tg = (const float*)d_in[1];
    const float *w[5], *g[4], *bb[4], *mm[4], *vv[4], *b_out;

    bool inter = (n_in > 3) && (in_sizes[3] == 64);
    if (inter) {
        for (int i = 0; i < 4; i++) {
            w[i]  = (const float*)d_in[2 + 5 * i];
            g[i]  = (const float*)d_in[3 + 5 * i];
            bb[i] = (const float*)d_in[4 + 5 * i];
            mm[i] = (const float*)d_in[5 + 5 * i];
            vv[i] = (const float*)d_in[6 + 5 * i];
        }
    } else {
        for (int i = 0; i < 4; i++) {
            w[i]  = (const float*)d_in[2 + i];
            g[i]  = (const float*)d_in[6 + i];
            bb[i] = (const float*)d_in[10 + i];
            mm[i] = (const float*)d_in[14 + i];
            vv[i] = (const float*)d_in[18 + i];
        }
    }
    w[4]  = (const float*)d_in[22];
    b_out = (const float*)d_in[23];

    float *bufA, *bufB, *wprep;
    double* accum;
    int* mask;
    cudaGetSymbolAddress((void**)&bufA, g_bufA);
    cudaGetSymbolAddress((void**)&bufB, g_bufB);
    cudaGetSymbolAddress((void**)&wprep, g_wprep);
    cudaGetSymbolAddress((void**)&accum, g_loss_accum);
    cudaGetSymbolAddress((void**)&mask, g_mask);

    // prepped-weight offsets (floats): CIN*10*COUTP per layer
    const size_t o0 = 0, o1 = 81920, o2 = 102400, o3 = 107520, o4 = 108800;

    constexpr int SM0 = conv_smem(128, 64, 1, 128, 8);
    constexpr int SM1 = conv_smem(64, 32, 2, 256, 8);
    constexpr int SM2 = conv_smem(32, 16, 4, 512, 8);
    constexpr int SM3 = conv_smem(16, 8, 8, 1024, 8);
    constexpr int SM4 = conv_smem(8, 3, 16, 1024, 8);
    constexpr int SMT = 3 * 8 * TTP * 4;

    cudaFuncSetAttribute(conv_layer<128, 64, 1, 128, 8, 8, true, false, 3>,
                         cudaFuncAttributeMaxDynamicSharedMemorySize, SM0);
    cudaFuncSetAttribute(conv_layer<64, 32, 2, 256, 8, 8, true, false, 4>,
                         cudaFuncAttributeMaxDynamicSharedMemorySize, SM1);
    cudaFuncSetAttribute(conv_layer<32, 16, 4, 512, 8, 8, true, false, 4>,
                         cudaFuncAttributeMaxDynamicSharedMemorySize, SM2);
    cudaFuncSetAttribute(conv_layer<16, 8, 8, 1024, 8, 8, true, false, 3>,
                         cudaFuncAttributeMaxDynamicSharedMemorySize, SM3);
    cudaFuncSetAttribute(conv_layer<8, 3, 16, 1024, 3, 8, false, true, 3>,
                         cudaFuncAttributeMaxDynamicSharedMemorySize, SM4);
    cudaFuncSetAttribute(transpose_loss,
                         cudaFuncAttributeMaxDynamicSharedMemorySize, SMT);

    prep_all<<<dim3(160, 6), 256>>>(w[0], w[1], w[2], w[3], w[4], wprep, accum, mask);

    conv_layer<128, 64, 1, 128, 8, 8, true, false, 3>
        <<<dim3(1024 / 128, BATCH), 256, SM0>>>(x, wprep + o0, g[0], bb[0], mm[0], vv[0],
                                                nullptr, bufA, 1024);
    conv_layer<64, 32, 2, 256, 8, 8, true, false, 4>
        <<<dim3(2048 / 256, BATCH), 256, SM1>>>(bufA, wprep + o1, g[1], bb[1], mm[1], vv[1],
                                                nullptr, bufB, 2048);
    conv_layer<32, 16, 4, 512, 8, 8, true, false, 4>
        <<<dim3(4096 / 512, BATCH), 256, SM2>>>(bufB, wprep + o2, g[2], bb[2], mm[2], vv[2],
                                                nullptr, bufA, 4096);
    conv_layer<16, 8, 8, 1024, 8, 8, true, false, 3>
        <<<dim3(8192 / 1024, BATCH), 256, SM3>>>(bufA, wprep + o3, g[3], bb[3], mm[3], vv[3],
                                                 nullptr, bufB, 8192);
    conv_layer<8, 3, 16, 1024, 3, 8, false, true, 3>
        <<<dim3(16384 / 1024, BATCH), 256, SM4>>>(bufB, wprep + o4, nullptr, nullptr, nullptr,
                                                  nullptr, b_out, bufA, 16384);

    transpose_loss<<<dim3(NT_OUT / TT, 32), 256, SMT>>>(bufA, tg, (float*)d_out,
                                                        accum, mask);
    finalize_kernel<<<1, 1>>>(accum, mask, (float*)d_out, out_size);
}

// round 11
// speedup vs baseline: 1.0925x; 1.0925x over previous
#include <cuda_runtime.h>
#include <stdint.h>
#include <math.h>

#define BATCH 256
#define NT_OUT 32768
#define OUT_ELEMS (32u * 3u * 32768u * 8u)   // 25,165,824

__device__ float g_bufA[BATCH * 64 * 2048];
__device__ float g_bufB[BATCH * 64 * 2048];
__device__ float g_wprep[131072];
__device__ double g_loss_accum;
__device__ int    g_mask[BATCH];

typedef unsigned long long u64;

__device__ __forceinline__ void fma2(u64 &d, u64 a, u64 b) {
    asm("fma.rn.f32x2 %0, %1, %2, %0;" : "+l"(d) : "l"(a), "l"(b));
}
__device__ __forceinline__ u64 pack2(float lo, float hi) {
    u64 r; asm("mov.b64 %0, {%1, %2};" : "=l"(r) : "f"(lo), "f"(hi)); return r;
}
__device__ __forceinline__ void unpack2(u64 v, float &lo, float &hi) {
    asm("mov.b64 {%0, %1}, %2;" : "=f"(lo), "=f"(hi) : "l"(v));
}
__device__ __forceinline__ unsigned sm_u32(const void* p) {
    unsigned a;
    asm("{.reg .u64 t; cvta.to.shared.u64 t, %1; cvt.u32.u64 %0, t;}"
        : "=r"(a) : "l"(p));
    return a;
}

// ---------------------------------------------------------------------------
// One prep kernel: all 5 layers' dup-pair weight reformat + accum/mask init.
// ---------------------------------------------------------------------------
__global__ void prep_all(const float* __restrict__ w0, const float* __restrict__ w1,
                         const float* __restrict__ w2, const float* __restrict__ w3,
                         const float* __restrict__ w4, float* __restrict__ wprep,
                         double* accum, int* mask)
{
    const int layer = blockIdx.y;
    if (layer == 5) {
        if (blockIdx.x == 0) {
            int t = threadIdx.x;
            if (t == 0) *accum = 0.0;
            if (t < BATCH) mask[t] = 0;
        }
        return;
    }
    const int CINs[5]   = {128, 64, 32, 16, 8};
    const int COUTs[5]  = {64, 32, 16, 8, 3};
    const int COUTPs[5] = {64, 32, 16, 8, 4};
    const int OFFs[5]   = {0, 81920, 102400, 107520, 108800};
    const float* W[5]   = {w0, w1, w2, w3, w4};
    const int CIN = CINs[layer], COUT = COUTs[layer], COUTP = COUTPs[layer];
    const int CHUNK = 8;
    const float* w = W[layer];
    float* dst = wprep + OFFs[layer];

    int n = COUT * CIN * 5;
    for (int idx = blockIdx.x * 256 + threadIdx.x; idx < n; idx += gridDim.x * 256) {
        int co = idx / (CIN * 5), r = idx - co * (CIN * 5);
        int ci = r / 5, k = r - ci * 5;
        int q = ci / CHUNK, cil = ci - q * CHUNK;
        float v = w[idx];
        int o = q * (CHUNK * 10 * COUTP) + (cil * 5 + k) * 2 * COUTP + 2 * co;
        dst[o] = v; dst[o + 1] = v;
    }
}

// ---------------------------------------------------------------------------
// WIDE conv (L0/L1/L2): RC=8 couts x RL=8 positions per thread, k-blocked
// X span in registers. cp.async double-buffer; smem W broadcast; shuffle up2.
// ---------------------------------------------------------------------------
template<int CIN, int COUT, int DIL, int TL, bool BN>
__global__ __launch_bounds__(256, 2)
void conv_wide(const float* __restrict__ x, const float* __restrict__ wp,
               const float* __restrict__ gg, const float* __restrict__ bb,
               const float* __restrict__ mm, const float* __restrict__ vv,
               float* __restrict__ y, int L)
{
    constexpr int RC = 8, CHUNK = 8;
    constexpr int PAD   = 2 * DIL;
    constexpr int HALO  = TL + 2 * PAD + 5;
    constexpr int HALOP = (HALO + 3) & ~3;
    constexpr int NPG   = TL / 8;
    constexpr int COUTP = COUT;                  // COUT is 64/32/16: already x4
    constexpr int WCH   = CHUNK * 10 * COUTP;
    constexpr int NCH   = CIN / CHUNK;
    constexpr int WPC   = NPG / 32;
    constexpr int SFT   = PAD + 4;

    const int tid  = threadIdx.x;
    const int tile = blockIdx.x;
    const int b    = blockIdx.y;
    const int pg   = tid % NPG;
    const int cg   = tid / NPG;
    const int lane = tid & 31;
    const int wic  = pg >> 5;
    const int lb   = pg * 8;
    const int cb   = cg * RC;

    extern __shared__ float sm[];
    float* Xbuf[2] = { sm, sm + CHUNK * HALOP };
    float* Wbuf[2] = { sm + 2 * CHUNK * HALOP, sm + 2 * CHUNK * HALOP + WCH };
    float* YsE   = sm + 2 * CHUNK * HALOP + 2 * WCH;   // [COUT][2]
    float* BndA3 = YsE + 2 * COUT;                     // [COUT][WPC]
    float* BndA0 = BndA3 + COUT * WPC;                 // [COUT][WPC]

    const float* xb    = x + (size_t)b * CIN * L;
    const int    gbase = tile * TL - SFT;

    u64 acc[RC][4];
#pragma unroll
    for (int q = 0; q < RC; q++)
#pragma unroll
        for (int j = 0; j < 4; j++) acc[q][j] = 0ull;

    float eacc = 0.f;
    const int eIdx = tid >> 1, eSide = tid & 1;
    int ej = 0;
    if (tid < 2 * COUT) {
        int gl = tile * TL + (eSide ? TL : -1);
        if (gl < 0)  gl = 0;
        if (gl >= L) gl = L - 1;
        ej = gl - tile * TL;
    }

    auto stage = [&](int p, int cc) {
        float* Xd = Xbuf[p];
        for (int idx = tid; idx < CHUNK * HALO; idx += 256) {
            int ci = idx / HALO, j = idx - ci * HALO;
            int gi = gbase + j;
            if (gi < 0)  gi = -gi;
            if (gi >= L) gi = 2 * L - 2 - gi;
            unsigned d = sm_u32(Xd + ci * HALOP + j);
            const float* s = xb + (size_t)(cc * CHUNK + ci) * L + gi;
            asm volatile("cp.async.ca.shared.global [%0], [%1], 4;" :: "r"(d), "l"(s));
        }
        const float4* wsrc = (const float4*)(wp + (size_t)cc * WCH);
        float* Wd = Wbuf[p];
        for (int idx = tid; idx < WCH / 4; idx += 256) {
            unsigned d = sm_u32(Wd + idx * 4);
            asm volatile("cp.async.cg.shared.global [%0], [%1], 16;"
                         :: "r"(d), "l"(wsrc + idx));
        }
        asm volatile("cp.async.commit_group;");
    };

    stage(0, 0);

    for (int cc = 0; cc < NCH; cc++) {
        const int p = cc & 1;
        asm volatile("cp.async.wait_group 0;");
        __syncthreads();
        if (cc + 1 < NCH) stage(p ^ 1, cc + 1);

        const float* Xs = Xbuf[p];
        const float* Ws = Wbuf[p];

#pragma unroll 1
        for (int ci = 0; ci < CHUNK; ci++) {
            const float* xr = Xs + ci * HALOP + lb + 4;
            if (DIL == 1) {
                ulonglong2 u0 = *(const ulonglong2*)xr;
                ulonglong2 u1 = *(const ulonglong2*)(xr + 4);
                ulonglong2 u2 = *(const ulonglong2*)(xr + 8);
                u64 A[6] = {u0.x, u0.y, u1.x, u1.y, u2.x, u2.y};
                float f[12];
#pragma unroll
                for (int i = 0; i < 6; i++) unpack2(A[i], f[2 * i], f[2 * i + 1]);
                u64 C[5];
#pragma unroll
                for (int i = 0; i < 5; i++) C[i] = pack2(f[2 * i + 1], f[2 * i + 2]);
#pragma unroll
                for (int k = 0; k < 5; k++) {
                    u64 xp[4];
#pragma unroll
                    for (int j = 0; j < 4; j++)
                        xp[j] = (k & 1) ? C[(k - 1) / 2 + j] : A[k / 2 + j];
                    const float* wr = Ws + (ci * 5 + k) * 2 * COUTP + 2 * cb;
#pragma unroll
                    for (int qq = 0; qq < 4; qq++) {
                        ulonglong2 wv = *(const ulonglong2*)(wr + 4 * qq);
#pragma unroll
                        for (int j = 0; j < 4; j++) {
                            fma2(acc[2 * qq][j], wv.x, xp[j]);
                            fma2(acc[2 * qq + 1][j], wv.y, xp[j]);
                        }
                    }
                }
            } else if (DIL == 2) {
                u64 S[8];
#pragma unroll
                for (int i = 0; i < 4; i++) {
                    ulonglong2 u = *(const ulonglong2*)(xr + 4 * i);
                    S[2 * i] = u.x; S[2 * i + 1] = u.y;
                }
#pragma unroll
                for (int k = 0; k < 5; k++) {
                    const float* wr = Ws + (ci * 5 + k) * 2 * COUTP + 2 * cb;
#pragma unroll
                    for (int qq = 0; qq < 4; qq++) {
                        ulonglong2 wv = *(const ulonglong2*)(wr + 4 * qq);
#pragma unroll
                        for (int j = 0; j < 4; j++) {
                            fma2(acc[2 * qq][j], wv.x, S[k + j]);
                            fma2(acc[2 * qq + 1][j], wv.y, S[k + j]);
                        }
                    }
                }
            } else {  // DIL == 4
                u64 S[12];
#pragma unroll
                for (int i = 0; i < 6; i++) {
                    ulonglong2 u = *(const ulonglong2*)(xr + 4 * i);
                    S[2 * i] = u.x; S[2 * i + 1] = u.y;
                }
#pragma unroll
                for (int k = 0; k < 5; k++) {
                    const float* wr = Ws + (ci * 5 + k) * 2 * COUTP + 2 * cb;
#pragma unroll
                    for (int qq = 0; qq < 4; qq++) {
                        ulonglong2 wv = *(const ulonglong2*)(wr + 4 * qq);
#pragma unroll
                        for (int j = 0; j < 4; j++) {
                            fma2(acc[2 * qq][j], wv.x, S[2 * k + j]);
                            fma2(acc[2 * qq + 1][j], wv.y, S[2 * k + j]);
                        }
                    }
                }
            }
        }

        if (tid < 2 * COUT) {
#pragma unroll 1
            for (int ci = 0; ci < CHUNK; ci++)
#pragma unroll
                for (int k = 0; k < 5; k++)
                    eacc = fmaf(Ws[(ci * 5 + k) * 2 * COUTP + 2 * eIdx],
                                Xs[ci * HALOP + ej + 4 + k * DIL], eacc);
        }
    }

    // ---- BN (+ReLU) into registers; publish boundary values ----
    float v[RC][8];
#pragma unroll
    for (int q = 0; q < RC; q++) {
        int c = cb + q;
        float inv = gg[c] * rsqrtf(vv[c] + 1e-5f);
        float sh  = bb[c] - mm[c] * inv;
#pragma unroll
        for (int j = 0; j < 4; j++) {
            float a0, a1;
            unpack2(acc[q][j], a0, a1);
            a0 = a0 * inv + sh; a1 = a1 * inv + sh;
            if (BN) { a0 = fmaxf(a0, 0.f); a1 = fmaxf(a1, 0.f); }
            v[q][2 * j] = a0; v[q][2 * j + 1] = a1;
        }
        if (lane == 31) BndA3[c * WPC + wic] = v[q][7];
        if (lane == 0)  BndA0[c * WPC + wic] = v[q][0];
    }
    if (tid < 2 * COUT) {
        int c = eIdx;
        float inv = gg[c] * rsqrtf(vv[c] + 1e-5f);
        float val = eacc * inv + bb[c] - mm[c] * inv;
        if (BN) val = fmaxf(val, 0.f);
        YsE[2 * c + eSide] = val;
    }
    __syncthreads();

    // ---- shuffle x2 upsample + coalesced store (16 outputs/thread/cout) ----
    const int Lup = 2 * L;
#pragma unroll
    for (int q = 0; q < RC; q++) {
        int c = cb + q;
        float yl = __shfl_up_sync(0xffffffffu, v[q][7], 1);
        float yr = __shfl_down_sync(0xffffffffu, v[q][0], 1);
        if (lane == 0)  yl = (wic == 0)       ? YsE[2 * c]     : BndA3[c * WPC + wic - 1];
        if (lane == 31) yr = (wic == WPC - 1) ? YsE[2 * c + 1] : BndA0[c * WPC + wic + 1];
        float o[16];
        o[0] = 0.25f * yl + 0.75f * v[q][0];
#pragma unroll
        for (int j = 1; j < 8; j++) o[2 * j] = 0.25f * v[q][j - 1] + 0.75f * v[q][j];
#pragma unroll
        for (int j = 0; j < 7; j++) o[2 * j + 1] = 0.75f * v[q][j] + 0.25f * v[q][j + 1];
        o[15] = 0.75f * v[q][7] + 0.25f * yr;
        size_t off = ((size_t)b * COUT + c) * Lup + 2 * (tile * TL + lb);
#pragma unroll
        for (int i = 0; i < 4; i++)
            *(float4*)(y + off + 4 * i) =
                make_float4(o[4 * i], o[4 * i + 1], o[4 * i + 2], o[4 * i + 3]);
    }
}

// ---------------------------------------------------------------------------
// Narrow conv (L3/L4): R9-proven RC x4 config.
// ---------------------------------------------------------------------------
template<int CIN, int COUT, int DIL, int TL, int RC, int CHUNK, bool BN, bool FINAL>
__global__ __launch_bounds__(256, 3)
void conv_layer(const float* __restrict__ x, const float* __restrict__ wp,
                const float* __restrict__ gg, const float* __restrict__ bb,
                const float* __restrict__ mm, const float* __restrict__ vv,
                const float* __restrict__ bout, float* __restrict__ y, int L)
{
    constexpr int PAD   = 2 * DIL;
    constexpr int SFT   = PAD + 4;
    constexpr int HALO  = TL + 2 * PAD + 5;
    constexpr int HALOP = (HALO + 3) & ~3;
    constexpr int NPG   = TL / 4;
    constexpr int COUTP = (COUT + 3) & ~3;
    constexpr int NQ    = (RC + 1) / 2;
    constexpr int WCH   = CHUNK * 10 * COUTP;
    constexpr int NCH   = CIN / CHUNK;
    constexpr int WPC   = NPG / 32;

    const int tid  = threadIdx.x;
    const int tile = blockIdx.x;
    const int b    = blockIdx.y;
    const int pg   = tid % NPG;
    const int cg   = tid / NPG;
    const int lane = tid & 31;
    const int wic  = pg >> 5;
    const int lb   = pg * 4;
    const int cb   = cg * RC;

    extern __shared__ float sm[];
    float* Xbuf[2] = { sm, sm + CHUNK * HALOP };
    float* Wbuf[2] = { sm + 2 * CHUNK * HALOP, sm + 2 * CHUNK * HALOP + WCH };
    float* YsE   = sm + 2 * CHUNK * HALOP + 2 * WCH;
    float* BndA3 = YsE + 2 * COUT;
    float* BndA0 = BndA3 + COUT * WPC;

    const float* xb    = x + (size_t)b * CIN * L;
    const int    gbase = tile * TL - SFT;

    u64 acc[RC][2];
#pragma unroll
    for (int q = 0; q < RC; q++) { acc[q][0] = 0ull; acc[q][1] = 0ull; }

    float eacc = 0.f;
    const int eIdx = tid >> 1, eSide = tid & 1;
    int ej = 0;
    if (tid < 2 * COUT) {
        int gl = tile * TL + (eSide ? TL : -1);
        if (gl < 0)  gl = 0;
        if (gl >= L) gl = L - 1;
        ej = gl - tile * TL;
    }

    auto stage = [&](int p, int cc) {
        float* Xd = Xbuf[p];
        for (int idx = tid; idx < CHUNK * HALO; idx += 256) {
            int ci = idx / HALO, j = idx - ci * HALO;
            int gi = gbase + j;
            if (gi < 0)  gi = -gi;
            if (gi >= L) gi = 2 * L - 2 - gi;
            unsigned d = sm_u32(Xd + ci * HALOP + j);
            const float* s = xb + (size_t)(cc * CHUNK + ci) * L + gi;
            asm volatile("cp.async.ca.shared.global [%0], [%1], 4;" :: "r"(d), "l"(s));
        }
        const float4* wsrc = (const float4*)(wp + (size_t)cc * WCH);
        float* Wd = Wbuf[p];
        for (int idx = tid; idx < WCH / 4; idx += 256) {
            unsigned d = sm_u32(Wd + idx * 4);
            asm volatile("cp.async.cg.shared.global [%0], [%1], 16;"
                         :: "r"(d), "l"(wsrc + idx));
        }
        asm volatile("cp.async.commit_group;");
    };

    stage(0, 0);

    for (int cc = 0; cc < NCH; cc++) {
        const int p = cc & 1;
        asm volatile("cp.async.wait_group 0;");
        __syncthreads();
        if (cc + 1 < NCH) stage(p ^ 1, cc + 1);

        const float* Xs = Xbuf[p];
        const float* Ws = Wbuf[p];

#pragma unroll 2
        for (int ci = 0; ci < CHUNK; ci++) {
            const float* xr = Xs + ci * HALOP + lb + 4;
#pragma unroll
            for (int k = 0; k < 5; k++) {
                ulonglong2 xv = *(const ulonglong2*)(xr + k * DIL);
                u64 xp0 = xv.x, xp1 = xv.y;
                const float* wr = Ws + (ci * 5 + k) * 2 * COUTP + 2 * cb;
#pragma unroll
                for (int qq = 0; qq < NQ; qq++) {
                    ulonglong2 wv = *(const ulonglong2*)(wr + 4 * qq);
                    fma2(acc[2 * qq][0], wv.x, xp0);
                    fma2(acc[2 * qq][1], wv.x, xp1);
                    if (2 * qq + 1 < RC) {
                        fma2(acc[2 * qq + 1][0], wv.y, xp0);
                        fma2(acc[2 * qq + 1][1], wv.y, xp1);
                    }
                }
            }
        }

        if (tid < 2 * COUT) {
#pragma unroll 1
            for (int ci = 0; ci < CHUNK; ci++)
#pragma unroll
                for (int k = 0; k < 5; k++)
                    eacc = fmaf(Ws[(ci * 5 + k) * 2 * COUTP + 2 * eIdx],
                                Xs[ci * HALOP + ej + 4 + k * DIL], eacc);
        }
    }

    float v[RC][4];
#pragma unroll
    for (int q = 0; q < RC; q++) {
        int c = cb + q;
        float sc, sh;
        if (FINAL) { sc = 1.f; sh = bout[c]; }
        else {
            float inv = gg[c] * rsqrtf(vv[c] + 1e-5f);
            sc = inv; sh = bb[c] - mm[c] * inv;
        }
        float a0, a1, a2, a3;
        unpack2(acc[q][0], a0, a1);
        unpack2(acc[q][1], a2, a3);
        a0 = a0 * sc + sh; a1 = a1 * sc + sh;
        a2 = a2 * sc + sh; a3 = a3 * sc + sh;
        if (BN) {
            a0 = fmaxf(a0, 0.f); a1 = fmaxf(a1, 0.f);
            a2 = fmaxf(a2, 0.f); a3 = fmaxf(a3, 0.f);
        }
        v[q][0] = a0; v[q][1] = a1; v[q][2] = a2; v[q][3] = a3;
        if (lane == 31) BndA3[c * WPC + wic] = a3;
        if (lane == 0)  BndA0[c * WPC + wic] = a0;
    }
    if (tid < 2 * COUT) {
        int c = eIdx;
        float sc, sh;
        if (FINAL) { sc = 1.f; sh = bout[c]; }
        else {
            float inv = gg[c] * rsqrtf(vv[c] + 1e-5f);
            sc = inv; sh = bb[c] - mm[c] * inv;
        }
        float val = eacc * sc + sh;
        if (BN) val = fmaxf(val, 0.f);
        YsE[2 * c + eSide] = val;
    }
    __syncthreads();

    const int Lup = 2 * L;
#pragma unroll
    for (int q = 0; q < RC; q++) {
        int c = cb + q;
        float yl = __shfl_up_sync(0xffffffffu, v[q][3], 1);
        float yr = __shfl_down_sync(0xffffffffu, v[q][0], 1);
        if (lane == 0)  yl = (wic == 0)       ? YsE[2 * c]     : BndA3[c * WPC + wic - 1];
        if (lane == 31) yr = (wic == WPC - 1) ? YsE[2 * c + 1] : BndA0[c * WPC + wic + 1];
        float y0 = v[q][0], y1 = v[q][1], y2 = v[q][2], y3 = v[q][3];
        float o0 = 0.25f * yl + 0.75f * y0, o1 = 0.75f * y0 + 0.25f * y1;
        float o2 = 0.25f * y0 + 0.75f * y1, o3 = 0.75f * y1 + 0.25f * y2;
        float o4 = 0.25f * y1 + 0.75f * y2, o5 = 0.75f * y2 + 0.25f * y3;
        float o6 = 0.25f * y2 + 0.75f * y3, o7 = 0.75f * y3 + 0.25f * yr;
        size_t off = ((size_t)b * COUT + c) * Lup + 2 * (tile * TL + lb);
        *(float4*)(y + off)     = make_float4(o0, o1, o2, o3);
        *(float4*)(y + off + 4) = make_float4(o4, o5, o6, o7);
    }
}

// ---------------------------------------------------------------------------
#define TT 512
#define TTP 516
__global__ __launch_bounds__(256)
void transpose_loss(const float* __restrict__ in, const float* __restrict__ tg,
                    float* __restrict__ out, double* accum, int* mask)
{
    const int bt = blockIdx.y;
    const int t0 = blockIdx.x * TT;
    const int tid = threadIdx.x;
    extern __shared__ float tile[];

    for (int idx = tid; idx < 3 * 8 * TT; idx += 256) {
        int c = idx / (8 * TT), r = idx - c * (8 * TT);
        int st = r / TT, t = r - st * TT;
        tile[(c * 8 + st) * TTP + t] =
            in[((size_t)(bt * 8 + st) * 3 + c) * NT_OUT + t0 + t];
    }
    __syncthreads();

    float s = 0.f;
    bool nz = false;
    const size_t ob = ((size_t)bt * 3) * NT_OUT * 8 + (size_t)t0 * 8;
    const size_t cs = (size_t)NT_OUT * 8;
#pragma unroll 4
    for (int i = 0; i < (TT * 8) / 256; i++) {
        int f = i * 256 + tid;
        int t = f >> 3, st = f & 7;
        float o0 = tile[(0 * 8 + st) * TTP + t];
        float o1 = tile[(1 * 8 + st) * TTP + t];
        float o2 = tile[(2 * 8 + st) * TTP + t];
        out[ob + f]          = o0;
        out[ob + cs + f]     = o1;
        out[ob + 2 * cs + f] = o2;
        float t0v = tg[ob + f], t1v = tg[ob + cs + f], t2v = tg[ob + 2 * cs + f];
        float mx  = fmaxf(o0, fmaxf(o1, o2));
        float lse = mx + __logf(__expf(o0 - mx) + __expf(o1 - mx) + __expf(o2 - mx));
        s += t0v * (lse - o0) + t1v * (lse - o1) + t2v * (lse - o2);
        nz = nz || (t0v != 0.f) || (t1v != 0.f) || (t2v != 0.f);
    }
    if (nz) atomicOr(&mask[bt * 8 + (tid & 7)], 1);

    __shared__ float red[256];
    red[tid] = s;
    __syncthreads();
    for (int o = 128; o > 0; o >>= 1) {
        if (tid < o) red[tid] += red[tid + o];
        __syncthreads();
    }
    if (tid == 0) atomicAdd(accum, (double)red[0]);
}

__global__ void finalize_kernel(const double* accum, const int* mask,
                                float* out, int out_size)
{
    if (threadIdx.x != 0 || blockIdx.x != 0) return;
    int num = 0;
    for (int i = 0; i < BATCH; i++) num += (mask[i] ? 1 : 0);
    double loss = *accum / ((double)num * (double)NT_OUT);
    if ((unsigned)out_size > OUT_ELEMS) out[OUT_ELEMS] = (float)loss;
}

// ---------------------------------------------------------------------------
static constexpr int wide_smem(int CIN, int COUT, int DIL, int TL) {
    int halop = ((TL + 4 * DIL + 5) + 3) & ~3;
    int wpc = (TL / 8) / 32;
    return (2 * 8 * halop + 2 * 8 * 10 * COUT + 2 * COUT + 2 * COUT * wpc) * 4;
}
static constexpr int narrow_smem(int CIN, int COUT, int DIL, int TL) {
    int halop = ((TL + 4 * DIL + 5) + 3) & ~3;
    int coutp = (COUT + 3) & ~3;
    int wpc = (TL / 4) / 32;
    return (2 * 8 * halop + 2 * 8 * 10 * coutp + 2 * COUT + 2 * COUT * wpc) * 4;
}

extern "C" void kernel_launch(void* const* d_in, const int* in_sizes, int n_in,
                              void* d_out, int out_size)
{
    const float* x  = (const float*)d_in[0];
    const float* tg = (const float*)d_in[1];
    const float *w[5], *g[4], *bb[4], *mm[4], *vv[4], *b_out;

    bool inter = (n_in > 3) && (in_sizes[3] == 64);
    if (inter) {
        for (int i = 0; i < 4; i++) {
            w[i]  = (const float*)d_in[2 + 5 * i];
            g[i]  = (const float*)d_in[3 + 5 * i];
            bb[i] = (const float*)d_in[4 + 5 * i];
            mm[i] = (const float*)d_in[5 + 5 * i];
            vv[i] = (const float*)d_in[6 + 5 * i];
        }
    } else {
        for (int i = 0; i < 4; i++) {
            w[i]  = (const float*)d_in[2 + i];
            g[i]  = (const float*)d_in[6 + i];
            bb[i] = (const float*)d_in[10 + i];
            mm[i] = (const float*)d_in[14 + i];
            vv[i] = (const float*)d_in[18 + i];
        }
    }
    w[4]  = (const float*)d_in[22];
    b_out = (const float*)d_in[23];

    float *bufA, *bufB, *wprep;
    double* accum;
    int* mask;
    cudaGetSymbolAddress((void**)&bufA, g_bufA);
    cudaGetSymbolAddress((void**)&bufB, g_bufB);
    cudaGetSymbolAddress((void**)&wprep, g_wprep);
    cudaGetSymbolAddress((void**)&accum, g_loss_accum);
    cudaGetSymbolAddress((void**)&mask, g_mask);

    const size_t o0 = 0, o1 = 81920, o2 = 102400, o3 = 107520, o4 = 108800;

    constexpr int SM0 = wide_smem(128, 64, 1, 256);
    constexpr int SM1 = wide_smem(64, 32, 2, 512);
    constexpr int SM2 = wide_smem(32, 16, 4, 1024);
    constexpr int SM3 = narrow_smem(16, 8, 8, 1024);
    constexpr int SM4 = narrow_smem(8, 3, 16, 1024);
    constexpr int SMT = 3 * 8 * TTP * 4;

    cudaFuncSetAttribute(conv_wide<128, 64, 1, 256, true>,
                         cudaFuncAttributeMaxDynamicSharedMemorySize, SM0);
    cudaFuncSetAttribute(conv_wide<64, 32, 2, 512, true>,
                         cudaFuncAttributeMaxDynamicSharedMemorySize, SM1);
    cudaFuncSetAttribute(conv_wide<32, 16, 4, 1024, true>,
                         cudaFuncAttributeMaxDynamicSharedMemorySize, SM2);
    cudaFuncSetAttribute(conv_layer<16, 8, 8, 1024, 8, 8, true, false>,
                         cudaFuncAttributeMaxDynamicSharedMemorySize, SM3);
    cudaFuncSetAttribute(conv_layer<8, 3, 16, 1024, 3, 8, false, true>,
                         cudaFuncAttributeMaxDynamicSharedMemorySize, SM4);
    cudaFuncSetAttribute(transpose_loss,
                         cudaFuncAttributeMaxDynamicSharedMemorySize, SMT);

    prep_all<<<dim3(160, 6), 256>>>(w[0], w[1], w[2], w[3], w[4], wprep, accum, mask);

    conv_wide<128, 64, 1, 256, true>
        <<<dim3(1024 / 256, BATCH), 256, SM0>>>(x, wprep + o0, g[0], bb[0], mm[0], vv[0],
                                                bufA, 1024);
    conv_wide<64, 32, 2, 512, true>
        <<<dim3(2048 / 512, BATCH), 256, SM1>>>(bufA, wprep + o1, g[1], bb[1], mm[1], vv[1],
                                                bufB, 2048);
    conv_wide<32, 16, 4, 1024, true>
        <<<dim3(4096 / 1024, BATCH), 256, SM2>>>(bufB, wprep + o2, g[2], bb[2], mm[2], vv[2],
                                                 bufA, 4096);
    conv_layer<16, 8, 8, 1024, 8, 8, true, false>
        <<<dim3(8192 / 1024, BATCH), 256, SM3>>>(bufA, wprep + o3, g[3], bb[3], mm[3], vv[3],
                                                 nullptr, bufB, 8192);
    conv_layer<8, 3, 16, 1024, 3, 8, false, true>
        <<<dim3(16384 / 1024, BATCH), 256, SM4>>>(bufB, wprep + o4, nullptr, nullptr, nullptr,
                                                  nullptr, b_out, bufA, 16384);

    transpose_loss<<<dim3(NT_OUT / TT, 32), 256, SMT>>>(bufA, tg, (float*)d_out,
                                                        accum, mask);
    finalize_kernel<<<1, 1>>>(accum, mask, (float*)d_out, out_size);
}

// round 13
// speedup vs baseline: 1.2222x; 1.1187x over previous
#include <cuda_runtime.h>
#include <stdint.h>
#include <math.h>

#define BATCH 256
#define NT_OUT 32768
#define OUT_ELEMS (32u * 3u * 32768u * 8u)   // 25,165,824

__device__ float g_bufA[BATCH * 64 * 2048];
__device__ float g_bufB[BATCH * 64 * 2048];
__device__ float g_wprep[131072];
__device__ double g_loss_accum;
__device__ int    g_mask[BATCH];

typedef unsigned long long u64;

__device__ __forceinline__ void fma2(u64 &d, u64 a, u64 b) {
    asm("fma.rn.f32x2 %0, %1, %2, %0;" : "+l"(d) : "l"(a), "l"(b));
}
__device__ __forceinline__ u64 pack2(float lo, float hi) {
    u64 r; asm("mov.b64 %0, {%1, %2};" : "=l"(r) : "f"(lo), "f"(hi)); return r;
}
__device__ __forceinline__ void unpack2(u64 v, float &lo, float &hi) {
    asm("mov.b64 {%0, %1}, %2;" : "=f"(lo), "=f"(hi) : "l"(v));
}
__device__ __forceinline__ unsigned sm_u32(const void* p) {
    unsigned a;
    asm("{.reg .u64 t; cvta.to.shared.u64 t, %1; cvt.u32.u64 %0, t;}"
        : "=r"(a) : "l"(p));
    return a;
}

// X staging: ci-outer, j-strided, vector cp.async for interior, scalar at edges.
template<int CHUNK, int HALO, int HALOP, int G>
__device__ __forceinline__ void stage_x(float* Xd, const float* xb, size_t Lstride,
                                        int cc, int gbase, int L, int tid)
{
#pragma unroll 1
    for (int ci = 0; ci < CHUNK; ci++) {
        const float* src = xb + (size_t)(cc * CHUNK + ci) * Lstride;
        float* dst = Xd + ci * HALOP;
#pragma unroll 1
        for (int j = tid * G; j < HALO; j += 256 * G) {
            int gi = gbase + j;
            if (gi >= 0 && gi + G <= L && j + G <= HALO) {
                unsigned d = sm_u32(dst + j);
                if (G == 4)
                    asm volatile("cp.async.ca.shared.global [%0], [%1], 16;"
                                 :: "r"(d), "l"(src + gi));
                else
                    asm volatile("cp.async.ca.shared.global [%0], [%1], 8;"
                                 :: "r"(d), "l"(src + gi));
            } else {
#pragma unroll
                for (int e = 0; e < G; e++) {
                    if (j + e < HALO) {
                        int g = gbase + j + e;
                        if (g < 0) g = -g;
                        if (g >= L) g = 2 * L - 2 - g;
                        unsigned d = sm_u32(dst + j + e);
                        asm volatile("cp.async.ca.shared.global [%0], [%1], 4;"
                                     :: "r"(d), "l"(src + g));
                    }
                }
            }
        }
    }
}

// ---------------------------------------------------------------------------
// One prep kernel: all 5 layers' dup-pair weight reformat + accum/mask init.
// ---------------------------------------------------------------------------
__global__ void prep_all(const float* __restrict__ w0, const float* __restrict__ w1,
                         const float* __restrict__ w2, const float* __restrict__ w3,
                         const float* __restrict__ w4, float* __restrict__ wprep,
                         double* accum, int* mask)
{
    const int layer = blockIdx.y;
    if (layer == 5) {
        if (blockIdx.x == 0) {
            int t = threadIdx.x;
            if (t == 0) *accum = 0.0;
            if (t < BATCH) mask[t] = 0;
        }
        return;
    }
    const int CINs[5]   = {128, 64, 32, 16, 8};
    const int COUTs[5]  = {64, 32, 16, 8, 3};
    const int COUTPs[5] = {64, 32, 16, 8, 4};
    const int OFFs[5]   = {0, 81920, 102400, 107520, 108800};
    const float* W[5]   = {w0, w1, w2, w3, w4};
    const int CIN = CINs[layer], COUT = COUTs[layer], COUTP = COUTPs[layer];
    const int CHUNK = 8;
    const float* w = W[layer];
    float* dst = wprep + OFFs[layer];

    int n = COUT * CIN * 5;
    for (int idx = blockIdx.x * 256 + threadIdx.x; idx < n; idx += gridDim.x * 256) {
        int co = idx / (CIN * 5), r = idx - co * (CIN * 5);
        int ci = r / 5, k = r - ci * 5;
        int q = ci / CHUNK, cil = ci - q * CHUNK;
        float v = w[idx];
        int o = q * (CHUNK * 10 * COUTP) + (cil * 5 + k) * 2 * COUTP + 2 * co;
        dst[o] = v; dst[o + 1] = v;
    }
}

// ---------------------------------------------------------------------------
// WIDE conv (L0/L1/L2): RC=8 x RL=8, k-blocked X span in registers.
// ---------------------------------------------------------------------------
template<int CIN, int COUT, int DIL, int TL, bool BN>
__global__ __launch_bounds__(256, 2)
void conv_wide(const float* __restrict__ x, const float* __restrict__ wp,
               const float* __restrict__ gg, const float* __restrict__ bb,
               const float* __restrict__ mm, const float* __restrict__ vv,
               float* __restrict__ y, int L)
{
    constexpr int RC = 8, CHUNK = 8;
    constexpr int PAD   = 2 * DIL;
    constexpr int HALO  = TL + 2 * PAD + 5;
    constexpr int HALOP = (HALO + 3) & ~3;
    constexpr int NPG   = TL / 8;
    constexpr int COUTP = COUT;
    constexpr int WCH   = CHUNK * 10 * COUTP;
    constexpr int NCH   = CIN / CHUNK;
    constexpr int WPC   = NPG / 32;
    constexpr int SFT   = PAD + 4;
    constexpr int G     = (DIL == 1) ? 2 : 4;

    const int tid  = threadIdx.x;
    const int tile = blockIdx.x;
    const int b    = blockIdx.y;
    const int pg   = tid % NPG;
    const int cg   = tid / NPG;
    const int lane = tid & 31;
    const int wic  = pg >> 5;
    const int lb   = pg * 8;
    const int cb   = cg * RC;

    extern __shared__ float sm[];
    float* Xbuf[2] = { sm, sm + CHUNK * HALOP };
    float* Wbuf[2] = { sm + 2 * CHUNK * HALOP, sm + 2 * CHUNK * HALOP + WCH };
    float* YsE   = sm + 2 * CHUNK * HALOP + 2 * WCH;
    float* BndA3 = YsE + 2 * COUT;
    float* BndA0 = BndA3 + COUT * WPC;

    const float* xb    = x + (size_t)b * CIN * L;
    const int    gbase = tile * TL - SFT;

    u64 acc[RC][4];
#pragma unroll
    for (int q = 0; q < RC; q++)
#pragma unroll
        for (int j = 0; j < 4; j++) acc[q][j] = 0ull;

    float eacc = 0.f;
    const int eIdx = tid >> 1, eSide = tid & 1;
    int ej = 0;
    if (tid < 2 * COUT) {
        int gl = tile * TL + (eSide ? TL : -1);
        if (gl < 0)  gl = 0;
        if (gl >= L) gl = L - 1;
        ej = gl - tile * TL;
    }

    auto stage = [&](int p, int cc) {
        stage_x<CHUNK, HALO, HALOP, G>(Xbuf[p], xb, L, cc, gbase, L, tid);
        const float4* wsrc = (const float4*)(wp + (size_t)cc * WCH);
        float* Wd = Wbuf[p];
        for (int idx = tid; idx < WCH / 4; idx += 256) {
            unsigned d = sm_u32(Wd + idx * 4);
            asm volatile("cp.async.cg.shared.global [%0], [%1], 16;"
                         :: "r"(d), "l"(wsrc + idx));
        }
        asm volatile("cp.async.commit_group;");
    };

    stage(0, 0);

    for (int cc = 0; cc < NCH; cc++) {
        const int p = cc & 1;
        asm volatile("cp.async.wait_group 0;");
        __syncthreads();
        if (cc + 1 < NCH) stage(p ^ 1, cc + 1);

        const float* Xs = Xbuf[p];
        const float* Ws = Wbuf[p];

#pragma unroll 1
        for (int ci = 0; ci < CHUNK; ci++) {
            const float* xr = Xs + ci * HALOP + lb + 4;
            if (DIL == 1) {
                ulonglong2 u0 = *(const ulonglong2*)xr;
                ulonglong2 u1 = *(const ulonglong2*)(xr + 4);
                ulonglong2 u2 = *(const ulonglong2*)(xr + 8);
                u64 A[6] = {u0.x, u0.y, u1.x, u1.y, u2.x, u2.y};
                float f[12];
#pragma unroll
                for (int i = 0; i < 6; i++) unpack2(A[i], f[2 * i], f[2 * i + 1]);
                u64 C[5];
#pragma unroll
                for (int i = 0; i < 5; i++) C[i] = pack2(f[2 * i + 1], f[2 * i + 2]);
#pragma unroll
                for (int k = 0; k < 5; k++) {
                    u64 xp[4];
#pragma unroll
                    for (int j = 0; j < 4; j++)
                        xp[j] = (k & 1) ? C[(k - 1) / 2 + j] : A[k / 2 + j];
                    const float* wr = Ws + (ci * 5 + k) * 2 * COUTP + 2 * cb;
#pragma unroll
                    for (int qq = 0; qq < 4; qq++) {
                        ulonglong2 wv = *(const ulonglong2*)(wr + 4 * qq);
#pragma unroll
                        for (int j = 0; j < 4; j++) {
                            fma2(acc[2 * qq][j], wv.x, xp[j]);
                            fma2(acc[2 * qq + 1][j], wv.y, xp[j]);
                        }
                    }
                }
            } else if (DIL == 2) {
                u64 S[8];
#pragma unroll
                for (int i = 0; i < 4; i++) {
                    ulonglong2 u = *(const ulonglong2*)(xr + 4 * i);
                    S[2 * i] = u.x; S[2 * i + 1] = u.y;
                }
#pragma unroll
                for (int k = 0; k < 5; k++) {
                    const float* wr = Ws + (ci * 5 + k) * 2 * COUTP + 2 * cb;
#pragma unroll
                    for (int qq = 0; qq < 4; qq++) {
                        ulonglong2 wv = *(const ulonglong2*)(wr + 4 * qq);
#pragma unroll
                        for (int j = 0; j < 4; j++) {
                            fma2(acc[2 * qq][j], wv.x, S[k + j]);
                            fma2(acc[2 * qq + 1][j], wv.y, S[k + j]);
                        }
                    }
                }
            } else {  // DIL == 4
                u64 S[12];
#pragma unroll
                for (int i = 0; i < 6; i++) {
                    ulonglong2 u = *(const ulonglong2*)(xr + 4 * i);
                    S[2 * i] = u.x; S[2 * i + 1] = u.y;
                }
#pragma unroll
                for (int k = 0; k < 5; k++) {
                    const float* wr = Ws + (ci * 5 + k) * 2 * COUTP + 2 * cb;
#pragma unroll
                    for (int qq = 0; qq < 4; qq++) {
                        ulonglong2 wv = *(const ulonglong2*)(wr + 4 * qq);
#pragma unroll
                        for (int j = 0; j < 4; j++) {
                            fma2(acc[2 * qq][j], wv.x, S[2 * k + j]);
                            fma2(acc[2 * qq + 1][j], wv.y, S[2 * k + j]);
                        }
                    }
                }
            }
        }

        if (tid < 2 * COUT) {
#pragma unroll 1
            for (int ci = 0; ci < CHUNK; ci++)
#pragma unroll
                for (int k = 0; k < 5; k++)
                    eacc = fmaf(Ws[(ci * 5 + k) * 2 * COUTP + 2 * eIdx],
                                Xs[ci * HALOP + ej + 4 + k * DIL], eacc);
        }
    }

    float v[RC][8];
#pragma unroll
    for (int q = 0; q < RC; q++) {
        int c = cb + q;
        float inv = gg[c] * rsqrtf(vv[c] + 1e-5f);
        float sh  = bb[c] - mm[c] * inv;
#pragma unroll
        for (int j = 0; j < 4; j++) {
            float a0, a1;
            unpack2(acc[q][j], a0, a1);
            a0 = a0 * inv + sh; a1 = a1 * inv + sh;
            if (BN) { a0 = fmaxf(a0, 0.f); a1 = fmaxf(a1, 0.f); }
            v[q][2 * j] = a0; v[q][2 * j + 1] = a1;
        }
        if (lane == 31) BndA3[c * WPC + wic] = v[q][7];
        if (lane == 0)  BndA0[c * WPC + wic] = v[q][0];
    }
    if (tid < 2 * COUT) {
        int c = eIdx;
        float inv = gg[c] * rsqrtf(vv[c] + 1e-5f);
        float val = eacc * inv + bb[c] - mm[c] * inv;
        if (BN) val = fmaxf(val, 0.f);
        YsE[2 * c + eSide] = val;
    }
    __syncthreads();

    const int Lup = 2 * L;
#pragma unroll
    for (int q = 0; q < RC; q++) {
        int c = cb + q;
        float yl = __shfl_up_sync(0xffffffffu, v[q][7], 1);
        float yr = __shfl_down_sync(0xffffffffu, v[q][0], 1);
        if (lane == 0)  yl = (wic == 0)       ? YsE[2 * c]     : BndA3[c * WPC + wic - 1];
        if (lane == 31) yr = (wic == WPC - 1) ? YsE[2 * c + 1] : BndA0[c * WPC + wic + 1];
        float o[16];
        o[0] = 0.25f * yl + 0.75f * v[q][0];
#pragma unroll
        for (int j = 1; j < 8; j++) o[2 * j] = 0.25f * v[q][j - 1] + 0.75f * v[q][j];
#pragma unroll
        for (int j = 0; j < 7; j++) o[2 * j + 1] = 0.75f * v[q][j] + 0.25f * v[q][j + 1];
        o[15] = 0.75f * v[q][7] + 0.25f * yr;
        size_t off = ((size_t)b * COUT + c) * Lup + 2 * (tile * TL + lb);
#pragma unroll
        for (int i = 0; i < 4; i++)
            *(float4*)(y + off + 4 * i) =
                make_float4(o[4 * i], o[4 * i + 1], o[4 * i + 2], o[4 * i + 3]);
    }
}

// ---------------------------------------------------------------------------
// Narrow conv (L3/L4): R9-proven RC x4 config.
// ---------------------------------------------------------------------------
template<int CIN, int COUT, int DIL, int TL, int RC, int CHUNK, bool BN, bool FINAL>
__global__ __launch_bounds__(256, 3)
void conv_layer(const float* __restrict__ x, const float* __restrict__ wp,
                const float* __restrict__ gg, const float* __restrict__ bb,
                const float* __restrict__ mm, const float* __restrict__ vv,
                const float* __restrict__ bout, float* __restrict__ y, int L)
{
    constexpr int PAD   = 2 * DIL;
    constexpr int SFT   = PAD + 4;
    constexpr int HALO  = TL + 2 * PAD + 5;
    constexpr int HALOP = (HALO + 3) & ~3;
    constexpr int NPG   = TL / 4;
    constexpr int COUTP = (COUT + 3) & ~3;
    constexpr int NQ    = (RC + 1) / 2;
    constexpr int WCH   = CHUNK * 10 * COUTP;
    constexpr int NCH   = CIN / CHUNK;
    constexpr int WPC   = NPG / 32;

    const int tid  = threadIdx.x;
    const int tile = blockIdx.x;
    const int b    = blockIdx.y;
    const int pg   = tid % NPG;
    const int cg   = tid / NPG;
    const int lane = tid & 31;
    const int wic  = pg >> 5;
    const int lb   = pg * 4;
    const int cb   = cg * RC;

    extern __shared__ float sm[];
    float* Xbuf[2] = { sm, sm + CHUNK * HALOP };
    float* Wbuf[2] = { sm + 2 * CHUNK * HALOP, sm + 2 * CHUNK * HALOP + WCH };
    float* YsE   = sm + 2 * CHUNK * HALOP + 2 * WCH;
    float* BndA3 = YsE + 2 * COUT;
    float* BndA0 = BndA3 + COUT * WPC;

    const float* xb    = x + (size_t)b * CIN * L;
    const int    gbase = tile * TL - SFT;

    u64 acc[RC][2];
#pragma unroll
    for (int q = 0; q < RC; q++) { acc[q][0] = 0ull; acc[q][1] = 0ull; }

    float eacc = 0.f;
    const int eIdx = tid >> 1, eSide = tid & 1;
    int ej = 0;
    if (tid < 2 * COUT) {
        int gl = tile * TL + (eSide ? TL : -1);
        if (gl < 0)  gl = 0;
        if (gl >= L) gl = L - 1;
        ej = gl - tile * TL;
    }

    auto stage = [&](int p, int cc) {
        stage_x<CHUNK, HALO, HALOP, 4>(Xbuf[p], xb, L, cc, gbase, L, tid);
        const float4* wsrc = (const float4*)(wp + (size_t)cc * WCH);
        float* Wd = Wbuf[p];
        for (int idx = tid; idx < WCH / 4; idx += 256) {
            unsigned d = sm_u32(Wd + idx * 4);
            asm volatile("cp.async.cg.shared.global [%0], [%1], 16;"
                         :: "r"(d), "l"(wsrc + idx));
        }
        asm volatile("cp.async.commit_group;");
    };

    stage(0, 0);

    for (int cc = 0; cc < NCH; cc++) {
        const int p = cc & 1;
        asm volatile("cp.async.wait_group 0;");
        __syncthreads();
        if (cc + 1 < NCH) stage(p ^ 1, cc + 1);

        const float* Xs = Xbuf[p];
        const float* Ws = Wbuf[p];

#pragma unroll 2
        for (int ci = 0; ci < CHUNK; ci++) {
            const float* xr = Xs + ci * HALOP + lb + 4;
#pragma unroll
            for (int k = 0; k < 5; k++) {
                ulonglong2 xv = *(const ulonglong2*)(xr + k * DIL);
                u64 xp0 = xv.x, xp1 = xv.y;
                const float* wr = Ws + (ci * 5 + k) * 2 * COUTP + 2 * cb;
#pragma unroll
                for (int qq = 0; qq < NQ; qq++) {
                    ulonglong2 wv = *(const ulonglong2*)(wr + 4 * qq);
                    fma2(acc[2 * qq][0], wv.x, xp0);
                    fma2(acc[2 * qq][1], wv.x, xp1);
                    if (2 * qq + 1 < RC) {
                        fma2(acc[2 * qq + 1][0], wv.y, xp0);
                        fma2(acc[2 * qq + 1][1], wv.y, xp1);
                    }
                }
            }
        }

        if (tid < 2 * COUT) {
#pragma unroll 1
            for (int ci = 0; ci < CHUNK; ci++)
#pragma unroll
                for (int k = 0; k < 5; k++)
                    eacc = fmaf(Ws[(ci * 5 + k) * 2 * COUTP + 2 * eIdx],
                                Xs[ci * HALOP + ej + 4 + k * DIL], eacc);
        }
    }

    float v[RC][4];
#pragma unroll
    for (int q = 0; q < RC; q++) {
        int c = cb + q;
        float sc, sh;
        if (FINAL) { sc = 1.f; sh = bout[c]; }
        else {
            float inv = gg[c] * rsqrtf(vv[c] + 1e-5f);
            sc = inv; sh = bb[c] - mm[c] * inv;
        }
        float a0, a1, a2, a3;
        unpack2(acc[q][0], a0, a1);
        unpack2(acc[q][1], a2, a3);
        a0 = a0 * sc + sh; a1 = a1 * sc + sh;
        a2 = a2 * sc + sh; a3 = a3 * sc + sh;
        if (BN) {
            a0 = fmaxf(a0, 0.f); a1 = fmaxf(a1, 0.f);
            a2 = fmaxf(a2, 0.f); a3 = fmaxf(a3, 0.f);
        }
        v[q][0] = a0; v[q][1] = a1; v[q][2] = a2; v[q][3] = a3;
        if (lane == 31) BndA3[c * WPC + wic] = a3;
        if (lane == 0)  BndA0[c * WPC + wic] = a0;
    }
    if (tid < 2 * COUT) {
        int c = eIdx;
        float sc, sh;
        if (FINAL) { sc = 1.f; sh = bout[c]; }
        else {
            float inv = gg[c] * rsqrtf(vv[c] + 1e-5f);
            sc = inv; sh = bb[c] - mm[c] * inv;
        }
        float val = eacc * sc + sh;
        if (BN) val = fmaxf(val, 0.f);
        YsE[2 * c + eSide] = val;
    }
    __syncthreads();

    const int Lup = 2 * L;
#pragma unroll
    for (int q = 0; q < RC; q++) {
        int c = cb + q;
        float yl = __shfl_up_sync(0xffffffffu, v[q][3], 1);
        float yr = __shfl_down_sync(0xffffffffu, v[q][0], 1);
        if (lane == 0)  yl = (wic == 0)       ? YsE[2 * c]     : BndA3[c * WPC + wic - 1];
        if (lane == 31) yr = (wic == WPC - 1) ? YsE[2 * c + 1] : BndA0[c * WPC + wic + 1];
        float y0 = v[q][0], y1 = v[q][1], y2 = v[q][2], y3 = v[q][3];
        float o0 = 0.25f * yl + 0.75f * y0, o1 = 0.75f * y0 + 0.25f * y1;
        float o2 = 0.25f * y0 + 0.75f * y1, o3 = 0.75f * y1 + 0.25f * y2;
        float o4 = 0.25f * y1 + 0.75f * y2, o5 = 0.75f * y2 + 0.25f * y3;
        float o6 = 0.25f * y2 + 0.75f * y3, o7 = 0.75f * y3 + 0.25f * yr;
        size_t off = ((size_t)b * COUT + c) * Lup + 2 * (tile * TL + lb);
        *(float4*)(y + off)     = make_float4(o0, o1, o2, o3);
        *(float4*)(y + off + 4) = make_float4(o4, o5, o6, o7);
    }
}

// ---------------------------------------------------------------------------
#define TT 512
#define TTP 516
__global__ __launch_bounds__(256)
void transpose_loss(const float* __restrict__ in, const float* __restrict__ tg,
                    float* __restrict__ out, double* accum, int* mask)
{
    const int bt = blockIdx.y;
    const int t0 = blockIdx.x * TT;
    const int tid = threadIdx.x;
    extern __shared__ float tile[];

    for (int idx = tid; idx < 3 * 8 * TT; idx += 256) {
        int c = idx / (8 * TT), r = idx - c * (8 * TT);
        int st = r / TT, t = r - st * TT;
        tile[(c * 8 + st) * TTP + t] =
            in[((size_t)(bt * 8 + st) * 3 + c) * NT_OUT + t0 + t];
    }
    __syncthreads();

    float s = 0.f;
    bool nz = false;
    const size_t ob = ((size_t)bt * 3) * NT_OUT * 8 + (size_t)t0 * 8;
    const size_t cs = (size_t)NT_OUT * 8;
#pragma unroll 4
    for (int i = 0; i < (TT * 8) / 256; i++) {
        int f = i * 256 + tid;
        int t = f >> 3, st = f & 7;
        float o0 = tile[(0 * 8 + st) * TTP + t];
        float o1 = tile[(1 * 8 + st) * TTP + t];
        float o2 = tile[(2 * 8 + st) * TTP + t];
        out[ob + f]          = o0;
        out[ob + cs + f]     = o1;
        out[ob + 2 * cs + f] = o2;
        float t0v = tg[ob + f], t1v = tg[ob + cs + f], t2v = tg[ob + 2 * cs + f];
        float mx  = fmaxf(o0, fmaxf(o1, o2));
        float lse = mx + __logf(__expf(o0 - mx) + __expf(o1 - mx) + __expf(o2 - mx));
        s += t0v * (lse - o0) + t1v * (lse - o1) + t2v * (lse - o2);
        nz = nz || (t0v != 0.f) || (t1v != 0.f) || (t2v != 0.f);
    }
    if (nz) atomicOr(&mask[bt * 8 + (tid & 7)], 1);

    __shared__ float red[256];
    red[tid] = s;
    __syncthreads();
    for (int o = 128; o > 0; o >>= 1) {
        if (tid < o) red[tid] += red[tid + o];
        __syncthreads();
    }
    if (tid == 0) atomicAdd(accum, (double)red[0]);
}

__global__ void finalize_kernel(const double* accum, const int* mask,
                                float* out, int out_size)
{
    if (threadIdx.x != 0 || blockIdx.x != 0) return;
    int num = 0;
    for (int i = 0; i < BATCH; i++) num += (mask[i] ? 1 : 0);
    double loss = *accum / ((double)num * (double)NT_OUT);
    if ((unsigned)out_size > OUT_ELEMS) out[OUT_ELEMS] = (float)loss;
}

// ---------------------------------------------------------------------------
static constexpr int wide_smem(int CIN, int COUT, int DIL, int TL) {
    int halop = ((TL + 4 * DIL + 5) + 3) & ~3;
    int wpc = (TL / 8) / 32;
    return (2 * 8 * halop + 2 * 8 * 10 * COUT + 2 * COUT + 2 * COUT * wpc) * 4;
}
static constexpr int narrow_smem(int CIN, int COUT, int DIL, int TL) {
    int halop = ((TL + 4 * DIL + 5) + 3) & ~3;
    int coutp = (COUT + 3) & ~3;
    int wpc = (TL / 4) / 32;
    return (2 * 8 * halop + 2 * 8 * 10 * coutp + 2 * COUT + 2 * COUT * wpc) * 4;
}

extern "C" void kernel_launch(void* const* d_in, const int* in_sizes, int n_in,
                              void* d_out, int out_size)
{
    const float* x  = (const float*)d_in[0];
    const float* tg = (const float*)d_in[1];
    const float *w[5], *g[4], *bb[4], *mm[4], *vv[4], *b_out;

    bool inter = (n_in > 3) && (in_sizes[3] == 64);
    if (inter) {
        for (int i = 0; i < 4; i++) {
            w[i]  = (const float*)d_in[2 + 5 * i];
            g[i]  = (const float*)d_in[3 + 5 * i];
            bb[i] = (const float*)d_in[4 + 5 * i];
            mm[i] = (const float*)d_in[5 + 5 * i];
            vv[i] = (const float*)d_in[6 + 5 * i];
        }
    } else {
        for (int i = 0; i < 4; i++) {
            w[i]  = (const float*)d_in[2 + i];
            g[i]  = (const float*)d_in[6 + i];
            bb[i] = (const float*)d_in[10 + i];
            mm[i] = (const float*)d_in[14 + i];
            vv[i] = (const float*)d_in[18 + i];
        }
    }
    w[4]  = (const float*)d_in[22];
    b_out = (const float*)d_in[23];

    float *bufA, *bufB, *wprep;
    double* accum;
    int* mask;
    cudaGetSymbolAddress((void**)&bufA, g_bufA);
    cudaGetSymbolAddress((void**)&bufB, g_bufB);
    cudaGetSymbolAddress((void**)&wprep, g_wprep);
    cudaGetSymbolAddress((void**)&accum, g_loss_accum);
    cudaGetSymbolAddress((void**)&mask, g_mask);

    const size_t o0 = 0, o1 = 81920, o2 = 102400, o3 = 107520, o4 = 108800;

    constexpr int SM0 = wide_smem(128, 64, 1, 256);
    constexpr int SM1 = wide_smem(64, 32, 2, 512);
    constexpr int SM2 = wide_smem(32, 16, 4, 1024);
    constexpr int SM3 = narrow_smem(16, 8, 8, 1024);
    constexpr int SM4 = narrow_smem(8, 3, 16, 1024);
    constexpr int SMT = 3 * 8 * TTP * 4;

    cudaFuncSetAttribute(conv_wide<128, 64, 1, 256, true>,
                         cudaFuncAttributeMaxDynamicSharedMemorySize, SM0);
    cudaFuncSetAttribute(conv_wide<64, 32, 2, 512, true>,
                         cudaFuncAttributeMaxDynamicSharedMemorySize, SM1);
    cudaFuncSetAttribute(conv_wide<32, 16, 4, 1024, true>,
                         cudaFuncAttributeMaxDynamicSharedMemorySize, SM2);
    cudaFuncSetAttribute(conv_layer<16, 8, 8, 1024, 8, 8, true, false>,
                         cudaFuncAttributeMaxDynamicSharedMemorySize, SM3);
    cudaFuncSetAttribute(conv_layer<8, 3, 16, 1024, 3, 8, false, true>,
                         cudaFuncAttributeMaxDynamicSharedMemorySize, SM4);
    cudaFuncSetAttribute(transpose_loss,
                         cudaFuncAttributeMaxDynamicSharedMemorySize, SMT);

    prep_all<<<dim3(160, 6), 256>>>(w[0], w[1], w[2], w[3], w[4], wprep, accum, mask);

    conv_wide<128, 64, 1, 256, true>
        <<<dim3(1024 / 256, BATCH), 256, SM0>>>(x, wprep + o0, g[0], bb[0], mm[0], vv[0],
                                                bufA, 1024);
    conv_wide<64, 32, 2, 512, true>
        <<<dim3(2048 / 512, BATCH), 256, SM1>>>(bufA, wprep + o1, g[1], bb[1], mm[1], vv[1],
                                                bufB, 2048);
    conv_wide<32, 16, 4, 1024, true>
        <<<dim3(4096 / 1024, BATCH), 256, SM2>>>(bufB, wprep + o2, g[2], bb[2], mm[2], vv[2],
                                                 bufA, 4096);
    conv_layer<16, 8, 8, 1024, 8, 8, true, false>
        <<<dim3(8192 / 1024, BATCH), 256, SM3>>>(bufA, wprep + o3, g[3], bb[3], mm[3], vv[3],
                                                 nullptr, bufB, 8192);
    conv_layer<8, 3, 16, 1024, 3, 8, false, true>
        <<<dim3(16384 / 1024, BATCH), 256, SM4>>>(bufB, wprep + o4, nullptr, nullptr, nullptr,
                                                  nullptr, b_out, bufA, 16384);

    transpose_loss<<<dim3(NT_OUT / TT, 32), 256, SMT>>>(bufA, tg, (float*)d_out,
                                                        accum, mask);
    finalize_kernel<<<1, 1>>>(accum, mask, (float*)d_out, out_size);
}

// round 14
// speedup vs baseline: 1.2233x; 1.0009x over previous
#include <cuda_runtime.h>
#include <stdint.h>
#include <math.h>

#define BATCH 256
#define NT_OUT 32768
#define OUT_ELEMS (32u * 3u * 32768u * 8u)   // 25,165,824

__device__ float g_bufA[BATCH * 64 * 2048];
__device__ float g_bufB[BATCH * 64 * 2048];
__device__ float g_wprep[131072];
__device__ double g_loss_accum;
__device__ int    g_mask[BATCH];

typedef unsigned long long u64;

__device__ __forceinline__ void fma2(u64 &d, u64 a, u64 b) {
    asm("fma.rn.f32x2 %0, %1, %2, %0;" : "+l"(d) : "l"(a), "l"(b));
}
__device__ __forceinline__ u64 pack2(float lo, float hi) {
    u64 r; asm("mov.b64 %0, {%1, %2};" : "=l"(r) : "f"(lo), "f"(hi)); return r;
}
__device__ __forceinline__ void unpack2(u64 v, float &lo, float &hi) {
    asm("mov.b64 {%0, %1}, %2;" : "=f"(lo), "=f"(hi) : "l"(v));
}
__device__ __forceinline__ unsigned sm_u32(const void* p) {
    unsigned a;
    asm("{.reg .u64 t; cvta.to.shared.u64 t, %1; cvt.u32.u64 %0, t;}"
        : "=r"(a) : "l"(p));
    return a;
}

// X staging: ci-outer, j-strided, vector cp.async for interior, scalar at edges.
template<int CHUNK, int HALO, int HALOP, int G>
__device__ __forceinline__ void stage_x(float* Xd, const float* xb, size_t Lstride,
                                        int cc, int gbase, int L, int tid)
{
#pragma unroll 1
    for (int ci = 0; ci < CHUNK; ci++) {
        const float* src = xb + (size_t)(cc * CHUNK + ci) * Lstride;
        float* dst = Xd + ci * HALOP;
#pragma unroll 1
        for (int j = tid * G; j < HALO; j += 256 * G) {
            int gi = gbase + j;
            if (gi >= 0 && gi + G <= L && j + G <= HALO) {
                unsigned d = sm_u32(dst + j);
                if (G == 4)
                    asm volatile("cp.async.ca.shared.global [%0], [%1], 16;"
                                 :: "r"(d), "l"(src + gi));
                else
                    asm volatile("cp.async.ca.shared.global [%0], [%1], 8;"
                                 :: "r"(d), "l"(src + gi));
            } else {
#pragma unroll
                for (int e = 0; e < G; e++) {
                    if (j + e < HALO) {
                        int g = gbase + j + e;
                        if (g < 0) g = -g;
                        if (g >= L) g = 2 * L - 2 - g;
                        unsigned d = sm_u32(dst + j + e);
                        asm volatile("cp.async.ca.shared.global [%0], [%1], 4;"
                                     :: "r"(d), "l"(src + g));
                    }
                }
            }
        }
    }
}

// ---------------------------------------------------------------------------
// One prep kernel: all 5 layers' dup-pair weight reformat + accum/mask init.
// ---------------------------------------------------------------------------
__global__ void prep_all(const float* __restrict__ w0, const float* __restrict__ w1,
                         const float* __restrict__ w2, const float* __restrict__ w3,
                         const float* __restrict__ w4, float* __restrict__ wprep,
                         double* accum, int* mask)
{
    const int layer = blockIdx.y;
    if (layer == 5) {
        if (blockIdx.x == 0) {
            int t = threadIdx.x;
            if (t == 0) *accum = 0.0;
            if (t < BATCH) mask[t] = 0;
        }
        return;
    }
    const int CINs[5]   = {128, 64, 32, 16, 8};
    const int COUTs[5]  = {64, 32, 16, 8, 3};
    const int COUTPs[5] = {64, 32, 16, 8, 4};
    const int OFFs[5]   = {0, 81920, 102400, 107520, 108800};
    const float* W[5]   = {w0, w1, w2, w3, w4};
    const int CIN = CINs[layer], COUT = COUTs[layer], COUTP = COUTPs[layer];
    const int CHUNK = 8;
    const float* w = W[layer];
    float* dst = wprep + OFFs[layer];

    int n = COUT * CIN * 5;
    for (int idx = blockIdx.x * 256 + threadIdx.x; idx < n; idx += gridDim.x * 256) {
        int co = idx / (CIN * 5), r = idx - co * (CIN * 5);
        int ci = r / 5, k = r - ci * 5;
        int q = ci / CHUNK, cil = ci - q * CHUNK;
        float v = w[idx];
        int o = q * (CHUNK * 10 * COUTP) + (cil * 5 + k) * 2 * COUTP + 2 * co;
        dst[o] = v; dst[o + 1] = v;
    }
}

// ---------------------------------------------------------------------------
// WIDE conv (L0/L1/L2): RC=8 x RL=8. Register-diet inner loops (no spills).
// ---------------------------------------------------------------------------
template<int CIN, int COUT, int DIL, int TL, bool BN>
__global__ __launch_bounds__(256, 2)
void conv_wide(const float* __restrict__ x, const float* __restrict__ wp,
               const float* __restrict__ gg, const float* __restrict__ bb,
               const float* __restrict__ mm, const float* __restrict__ vv,
               float* __restrict__ y, int L)
{
    constexpr int RC = 8, CHUNK = 8;
    constexpr int PAD   = 2 * DIL;
    constexpr int HALO  = TL + 2 * PAD + 5;
    constexpr int HALOP = (HALO + 3) & ~3;
    constexpr int NPG   = TL / 8;
    constexpr int COUTP = COUT;
    constexpr int WCH   = CHUNK * 10 * COUTP;
    constexpr int NCH   = CIN / CHUNK;
    constexpr int WPC   = NPG / 32;
    constexpr int SFT   = PAD + 4;
    constexpr int G     = (DIL == 1) ? 2 : 4;

    const int tid  = threadIdx.x;
    const int tile = blockIdx.x;
    const int b    = blockIdx.y;
    const int pg   = tid % NPG;
    const int cg   = tid / NPG;
    const int lane = tid & 31;
    const int wic  = pg >> 5;
    const int lb   = pg * 8;
    const int cb   = cg * RC;

    extern __shared__ float sm[];
    float* Xbuf[2] = { sm, sm + CHUNK * HALOP };
    float* Wbuf[2] = { sm + 2 * CHUNK * HALOP, sm + 2 * CHUNK * HALOP + WCH };
    float* YsE   = sm + 2 * CHUNK * HALOP + 2 * WCH;
    float* BndA3 = YsE + 2 * COUT;
    float* BndA0 = BndA3 + COUT * WPC;

    const float* xb    = x + (size_t)b * CIN * L;
    const int    gbase = tile * TL - SFT;

    u64 acc[RC][4];
#pragma unroll
    for (int q = 0; q < RC; q++)
#pragma unroll
        for (int j = 0; j < 4; j++) acc[q][j] = 0ull;

    float eacc = 0.f;
    const int eIdx = tid >> 1, eSide = tid & 1;
    int ej = 0;
    if (tid < 2 * COUT) {
        int gl = tile * TL + (eSide ? TL : -1);
        if (gl < 0)  gl = 0;
        if (gl >= L) gl = L - 1;
        ej = gl - tile * TL;
    }

    auto stage = [&](int p, int cc) {
        stage_x<CHUNK, HALO, HALOP, G>(Xbuf[p], xb, L, cc, gbase, L, tid);
        const float4* wsrc = (const float4*)(wp + (size_t)cc * WCH);
        float* Wd = Wbuf[p];
        for (int idx = tid; idx < WCH / 4; idx += 256) {
            unsigned d = sm_u32(Wd + idx * 4);
            asm volatile("cp.async.cg.shared.global [%0], [%1], 16;"
                         :: "r"(d), "l"(wsrc + idx));
        }
        asm volatile("cp.async.commit_group;");
    };

    stage(0, 0);

    for (int cc = 0; cc < NCH; cc++) {
        const int p = cc & 1;
        asm volatile("cp.async.wait_group 0;");
        __syncthreads();
        if (cc + 1 < NCH) stage(p ^ 1, cc + 1);

        const float* Xs = Xbuf[p];
        const float* Ws = Wbuf[p];

#pragma unroll 1
        for (int ci = 0; ci < CHUNK; ci++) {
            const float* xr = Xs + ci * HALOP + lb + 4;
            if (DIL == 1) {
                // keep only f[12]; build per-k pairs transiently
                float4 F0 = *(const float4*)xr;
                float4 F1 = *(const float4*)(xr + 4);
                float4 F2 = *(const float4*)(xr + 8);
                float f[12] = {F0.x, F0.y, F0.z, F0.w, F1.x, F1.y, F1.z, F1.w,
                               F2.x, F2.y, F2.z, F2.w};
#pragma unroll
                for (int k = 0; k < 5; k++) {
                    u64 xp[4];
#pragma unroll
                    for (int j = 0; j < 4; j++)
                        xp[j] = pack2(f[k + 2 * j], f[k + 2 * j + 1]);
                    const float* wr = Ws + (ci * 5 + k) * 2 * COUTP + 2 * cb;
#pragma unroll
                    for (int qq = 0; qq < 4; qq++) {
                        ulonglong2 wv = *(const ulonglong2*)(wr + 4 * qq);
#pragma unroll
                        for (int j = 0; j < 4; j++) {
                            fma2(acc[2 * qq][j], wv.x, xp[j]);
                            fma2(acc[2 * qq + 1][j], wv.y, xp[j]);
                        }
                    }
                }
            } else if (DIL == 2) {
                u64 S[8];
#pragma unroll
                for (int i = 0; i < 4; i++) {
                    ulonglong2 u = *(const ulonglong2*)(xr + 4 * i);
                    S[2 * i] = u.x; S[2 * i + 1] = u.y;
                }
#pragma unroll
                for (int k = 0; k < 5; k++) {
                    const float* wr = Ws + (ci * 5 + k) * 2 * COUTP + 2 * cb;
#pragma unroll
                    for (int qq = 0; qq < 4; qq++) {
                        ulonglong2 wv = *(const ulonglong2*)(wr + 4 * qq);
#pragma unroll
                        for (int j = 0; j < 4; j++) {
                            fma2(acc[2 * qq][j], wv.x, S[k + j]);
                            fma2(acc[2 * qq + 1][j], wv.y, S[k + j]);
                        }
                    }
                }
            } else {  // DIL == 4: per-k aligned loads, no persistent span
#pragma unroll
                for (int k = 0; k < 5; k++) {
                    ulonglong2 xa = *(const ulonglong2*)(xr + 4 * k);
                    ulonglong2 xc = *(const ulonglong2*)(xr + 4 * k + 4);
                    u64 xp[4] = {xa.x, xa.y, xc.x, xc.y};
                    const float* wr = Ws + (ci * 5 + k) * 2 * COUTP + 2 * cb;
#pragma unroll
                    for (int qq = 0; qq < 4; qq++) {
                        ulonglong2 wv = *(const ulonglong2*)(wr + 4 * qq);
#pragma unroll
                        for (int j = 0; j < 4; j++) {
                            fma2(acc[2 * qq][j], wv.x, xp[j]);
                            fma2(acc[2 * qq + 1][j], wv.y, xp[j]);
                        }
                    }
                }
            }
        }

        if (tid < 2 * COUT) {
#pragma unroll 1
            for (int ci = 0; ci < CHUNK; ci++)
#pragma unroll
                for (int k = 0; k < 5; k++)
                    eacc = fmaf(Ws[(ci * 5 + k) * 2 * COUTP + 2 * eIdx],
                                Xs[ci * HALOP + ej + 4 + k * DIL], eacc);
        }
    }

    float v[RC][8];
#pragma unroll
    for (int q = 0; q < RC; q++) {
        int c = cb + q;
        float inv = gg[c] * rsqrtf(vv[c] + 1e-5f);
        float sh  = bb[c] - mm[c] * inv;
#pragma unroll
        for (int j = 0; j < 4; j++) {
            float a0, a1;
            unpack2(acc[q][j], a0, a1);
            a0 = a0 * inv + sh; a1 = a1 * inv + sh;
            if (BN) { a0 = fmaxf(a0, 0.f); a1 = fmaxf(a1, 0.f); }
            v[q][2 * j] = a0; v[q][2 * j + 1] = a1;
        }
        if (lane == 31) BndA3[c * WPC + wic] = v[q][7];
        if (lane == 0)  BndA0[c * WPC + wic] = v[q][0];
    }
    if (tid < 2 * COUT) {
        int c = eIdx;
        float inv = gg[c] * rsqrtf(vv[c] + 1e-5f);
        float val = eacc * inv + bb[c] - mm[c] * inv;
        if (BN) val = fmaxf(val, 0.f);
        YsE[2 * c + eSide] = val;
    }
    __syncthreads();

    const int Lup = 2 * L;
#pragma unroll
    for (int q = 0; q < RC; q++) {
        int c = cb + q;
        float yl = __shfl_up_sync(0xffffffffu, v[q][7], 1);
        float yr = __shfl_down_sync(0xffffffffu, v[q][0], 1);
        if (lane == 0)  yl = (wic == 0)       ? YsE[2 * c]     : BndA3[c * WPC + wic - 1];
        if (lane == 31) yr = (wic == WPC - 1) ? YsE[2 * c + 1] : BndA0[c * WPC + wic + 1];
        float o[16];
        o[0] = 0.25f * yl + 0.75f * v[q][0];
#pragma unroll
        for (int j = 1; j < 8; j++) o[2 * j] = 0.25f * v[q][j - 1] + 0.75f * v[q][j];
#pragma unroll
        for (int j = 0; j < 7; j++) o[2 * j + 1] = 0.75f * v[q][j] + 0.25f * v[q][j + 1];
        o[15] = 0.75f * v[q][7] + 0.25f * yr;
        size_t off = ((size_t)b * COUT + c) * Lup + 2 * (tile * TL + lb);
#pragma unroll
        for (int i = 0; i < 4; i++)
            *(float4*)(y + off + 4 * i) =
                make_float4(o[4 * i], o[4 * i + 1], o[4 * i + 2], o[4 * i + 3]);
    }
}

// ---------------------------------------------------------------------------
// Narrow conv (L3/L4): R9-proven RC x4 config.
// ---------------------------------------------------------------------------
template<int CIN, int COUT, int DIL, int TL, int RC, int CHUNK, bool BN, bool FINAL>
__global__ __launch_bounds__(256, 3)
void conv_layer(const float* __restrict__ x, const float* __restrict__ wp,
                const float* __restrict__ gg, const float* __restrict__ bb,
                const float* __restrict__ mm, const float* __restrict__ vv,
                const float* __restrict__ bout, float* __restrict__ y, int L)
{
    constexpr int PAD   = 2 * DIL;
    constexpr int SFT   = PAD + 4;
    constexpr int HALO  = TL + 2 * PAD + 5;
    constexpr int HALOP = (HALO + 3) & ~3;
    constexpr int NPG   = TL / 4;
    constexpr int COUTP = (COUT + 3) & ~3;
    constexpr int NQ    = (RC + 1) / 2;
    constexpr int WCH   = CHUNK * 10 * COUTP;
    constexpr int NCH   = CIN / CHUNK;
    constexpr int WPC   = NPG / 32;

    const int tid  = threadIdx.x;
    const int tile = blockIdx.x;
    const int b    = blockIdx.y;
    const int pg   = tid % NPG;
    const int cg   = tid / NPG;
    const int lane = tid & 31;
    const int wic  = pg >> 5;
    const int lb   = pg * 4;
    const int cb   = cg * RC;

    extern __shared__ float sm[];
    float* Xbuf[2] = { sm, sm + CHUNK * HALOP };
    float* Wbuf[2] = { sm + 2 * CHUNK * HALOP, sm + 2 * CHUNK * HALOP + WCH };
    float* YsE   = sm + 2 * CHUNK * HALOP + 2 * WCH;
    float* BndA3 = YsE + 2 * COUT;
    float* BndA0 = BndA3 + COUT * WPC;

    const float* xb    = x + (size_t)b * CIN * L;
    const int    gbase = tile * TL - SFT;

    u64 acc[RC][2];
#pragma unroll
    for (int q = 0; q < RC; q++) { acc[q][0] = 0ull; acc[q][1] = 0ull; }

    float eacc = 0.f;
    const int eIdx = tid >> 1, eSide = tid & 1;
    int ej = 0;
    if (tid < 2 * COUT) {
        int gl = tile * TL + (eSide ? TL : -1);
        if (gl < 0)  gl = 0;
        if (gl >= L) gl = L - 1;
        ej = gl - tile * TL;
    }

    auto stage = [&](int p, int cc) {
        stage_x<CHUNK, HALO, HALOP, 4>(Xbuf[p], xb, L, cc, gbase, L, tid);
        const float4* wsrc = (const float4*)(wp + (size_t)cc * WCH);
        float* Wd = Wbuf[p];
        for (int idx = tid; idx < WCH / 4; idx += 256) {
            unsigned d = sm_u32(Wd + idx * 4);
            asm volatile("cp.async.cg.shared.global [%0], [%1], 16;"
                         :: "r"(d), "l"(wsrc + idx));
        }
        asm volatile("cp.async.commit_group;");
    };

    stage(0, 0);

    for (int cc = 0; cc < NCH; cc++) {
        const int p = cc & 1;
        asm volatile("cp.async.wait_group 0;");
        __syncthreads();
        if (cc + 1 < NCH) stage(p ^ 1, cc + 1);

        const float* Xs = Xbuf[p];
        const float* Ws = Wbuf[p];

#pragma unroll 2
        for (int ci = 0; ci < CHUNK; ci++) {
            const float* xr = Xs + ci * HALOP + lb + 4;
#pragma unroll
            for (int k = 0; k < 5; k++) {
                ulonglong2 xv = *(const ulonglong2*)(xr + k * DIL);
                u64 xp0 = xv.x, xp1 = xv.y;
                const float* wr = Ws + (ci * 5 + k) * 2 * COUTP + 2 * cb;
#pragma unroll
                for (int qq = 0; qq < NQ; qq++) {
                    ulonglong2 wv = *(const ulonglong2*)(wr + 4 * qq);
                    fma2(acc[2 * qq][0], wv.x, xp0);
                    fma2(acc[2 * qq][1], wv.x, xp1);
                    if (2 * qq + 1 < RC) {
                        fma2(acc[2 * qq + 1][0], wv.y, xp0);
                        fma2(acc[2 * qq + 1][1], wv.y, xp1);
                    }
                }
            }
        }

        if (tid < 2 * COUT) {
#pragma unroll 1
            for (int ci = 0; ci < CHUNK; ci++)
#pragma unroll
                for (int k = 0; k < 5; k++)
                    eacc = fmaf(Ws[(ci * 5 + k) * 2 * COUTP + 2 * eIdx],
                                Xs[ci * HALOP + ej + 4 + k * DIL], eacc);
        }
    }

    float v[RC][4];
#pragma unroll
    for (int q = 0; q < RC; q++) {
        int c = cb + q;
        float sc, sh;
        if (FINAL) { sc = 1.f; sh = bout[c]; }
        else {
            float inv = gg[c] * rsqrtf(vv[c] + 1e-5f);
            sc = inv; sh = bb[c] - mm[c] * inv;
        }
        float a0, a1, a2, a3;
        unpack2(acc[q][0], a0, a1);
        unpack2(acc[q][1], a2, a3);
        a0 = a0 * sc + sh; a1 = a1 * sc + sh;
        a2 = a2 * sc + sh; a3 = a3 * sc + sh;
        if (BN) {
            a0 = fmaxf(a0, 0.f); a1 = fmaxf(a1, 0.f);
            a2 = fmaxf(a2, 0.f); a3 = fmaxf(a3, 0.f);
        }
        v[q][0] = a0; v[q][1] = a1; v[q][2] = a2; v[q][3] = a3;
        if (lane == 31) BndA3[c * WPC + wic] = a3;
        if (lane == 0)  BndA0[c * WPC + wic] = a0;
    }
    if (tid < 2 * COUT) {
        int c = eIdx;
        float sc, sh;
        if (FINAL) { sc = 1.f; sh = bout[c]; }
        else {
            float inv = gg[c] * rsqrtf(vv[c] + 1e-5f);
            sc = inv; sh = bb[c] - mm[c] * inv;
        }
        float val = eacc * sc + sh;
        if (BN) val = fmaxf(val, 0.f);
        YsE[2 * c + eSide] = val;
    }
    __syncthreads();

    const int Lup = 2 * L;
#pragma unroll
    for (int q = 0; q < RC; q++) {
        int c = cb + q;
        float yl = __shfl_up_sync(0xffffffffu, v[q][3], 1);
        float yr = __shfl_down_sync(0xffffffffu, v[q][0], 1);
        if (lane == 0)  yl = (wic == 0)       ? YsE[2 * c]     : BndA3[c * WPC + wic - 1];
        if (lane == 31) yr = (wic == WPC - 1) ? YsE[2 * c + 1] : BndA0[c * WPC + wic + 1];
        float y0 = v[q][0], y1 = v[q][1], y2 = v[q][2], y3 = v[q][3];
        float o0 = 0.25f * yl + 0.75f * y0, o1 = 0.75f * y0 + 0.25f * y1;
        float o2 = 0.25f * y0 + 0.75f * y1, o3 = 0.75f * y1 + 0.25f * y2;
        float o4 = 0.25f * y1 + 0.75f * y2, o5 = 0.75f * y2 + 0.25f * y3;
        float o6 = 0.25f * y2 + 0.75f * y3, o7 = 0.75f * y3 + 0.25f * yr;
        size_t off = ((size_t)b * COUT + c) * Lup + 2 * (tile * TL + lb);
        *(float4*)(y + off)     = make_float4(o0, o1, o2, o3);
        *(float4*)(y + off + 4) = make_float4(o4, o5, o6, o7);
    }
}

// ---------------------------------------------------------------------------
#define TT 512
#define TTP 516
__global__ __launch_bounds__(256)
void transpose_loss(const float* __restrict__ in, const float* __restrict__ tg,
                    float* __restrict__ out, double* accum, int* mask)
{
    const int bt = blockIdx.y;
    const int t0 = blockIdx.x * TT;
    const int tid = threadIdx.x;
    extern __shared__ float tile[];

    for (int idx = tid; idx < 3 * 8 * TT; idx += 256) {
        int c = idx / (8 * TT), r = idx - c * (8 * TT);
        int st = r / TT, t = r - st * TT;
        tile[(c * 8 + st) * TTP + t] =
            in[((size_t)(bt * 8 + st) * 3 + c) * NT_OUT + t0 + t];
    }
    __syncthreads();

    float s = 0.f;
    bool nz = false;
    const size_t ob = ((size_t)bt * 3) * NT_OUT * 8 + (size_t)t0 * 8;
    const size_t cs = (size_t)NT_OUT * 8;
#pragma unroll 4
    for (int i = 0; i < (TT * 8) / 256; i++) {
        int f = i * 256 + tid;
        int t = f >> 3, st = f & 7;
        float o0 = tile[(0 * 8 + st) * TTP + t];
        float o1 = tile[(1 * 8 + st) * TTP + t];
        float o2 = tile[(2 * 8 + st) * TTP + t];
        out[ob + f]          = o0;
        out[ob + cs + f]     = o1;
        out[ob + 2 * cs + f] = o2;
        float t0v = tg[ob + f], t1v = tg[ob + cs + f], t2v = tg[ob + 2 * cs + f];
        float mx  = fmaxf(o0, fmaxf(o1, o2));
        float lse = mx + __logf(__expf(o0 - mx) + __expf(o1 - mx) + __expf(o2 - mx));
        s += t0v * (lse - o0) + t1v * (lse - o1) + t2v * (lse - o2);
        nz = nz || (t0v != 0.f) || (t1v != 0.f) || (t2v != 0.f);
    }
    if (nz) atomicOr(&mask[bt * 8 + (tid & 7)], 1);

    __shared__ float red[256];
    red[tid] = s;
    __syncthreads();
    for (int o = 128; o > 0; o >>= 1) {
        if (tid < o) red[tid] += red[tid + o];
        __syncthreads();
    }
    if (tid == 0) atomicAdd(accum, (double)red[0]);
}

__global__ void finalize_kernel(const double* accum, const int* mask,
                                float* out, int out_size)
{
    if (threadIdx.x != 0 || blockIdx.x != 0) return;
    int num = 0;
    for (int i = 0; i < BATCH; i++) num += (mask[i] ? 1 : 0);
    double loss = *accum / ((double)num * (double)NT_OUT);
    if ((unsigned)out_size > OUT_ELEMS) out[OUT_ELEMS] = (float)loss;
}

// ---------------------------------------------------------------------------
static constexpr int wide_smem(int CIN, int COUT, int DIL, int TL) {
    int halop = ((TL + 4 * DIL + 5) + 3) & ~3;
    int wpc = (TL / 8) / 32;
    return (2 * 8 * halop + 2 * 8 * 10 * COUT + 2 * COUT + 2 * COUT * wpc) * 4;
}
static constexpr int narrow_smem(int CIN, int COUT, int DIL, int TL) {
    int halop = ((TL + 4 * DIL + 5) + 3) & ~3;
    int coutp = (COUT + 3) & ~3;
    int wpc = (TL / 4) / 32;
    return (2 * 8 * halop + 2 * 8 * 10 * coutp + 2 * COUT + 2 * COUT * wpc) * 4;
}

extern "C" void kernel_launch(void* const* d_in, const int* in_sizes, int n_in,
                              void* d_out, int out_size)
{
    const float* x  = (const float*)d_in[0];
    const float* tg = (const float*)d_in[1];
    const float *w[5], *g[4], *bb[4], *mm[4], *vv[4], *b_out;

    bool inter = (n_in > 3) && (in_sizes[3] == 64);
    if (inter) {
        for (int i = 0; i < 4; i++) {
            w[i]  = (const float*)d_in[2 + 5 * i];
            g[i]  = (const float*)d_in[3 + 5 * i];
            bb[i] = (const float*)d_in[4 + 5 * i];
            mm[i] = (const float*)d_in[5 + 5 * i];
            vv[i] = (const float*)d_in[6 + 5 * i];
        }
    } else {
        for (int i = 0; i < 4; i++) {
            w[i]  = (const float*)d_in[2 + i];
            g[i]  = (const float*)d_in[6 + i];
            bb[i] = (const float*)d_in[10 + i];
            mm[i] = (const float*)d_in[14 + i];
            vv[i] = (const float*)d_in[18 + i];
        }
    }
    w[4]  = (const float*)d_in[22];
    b_out = (const float*)d_in[23];

    float *bufA, *bufB, *wprep;
    double* accum;
    int* mask;
    cudaGetSymbolAddress((void**)&bufA, g_bufA);
    cudaGetSymbolAddress((void**)&bufB, g_bufB);
    cudaGetSymbolAddress((void**)&wprep, g_wprep);
    cudaGetSymbolAddress((void**)&accum, g_loss_accum);
    cudaGetSymbolAddress((void**)&mask, g_mask);

    const size_t o0 = 0, o1 = 81920, o2 = 102400, o3 = 107520, o4 = 108800;

    constexpr int SM0 = wide_smem(128, 64, 1, 256);
    constexpr int SM1 = wide_smem(64, 32, 2, 512);
    constexpr int SM2 = wide_smem(32, 16, 4, 1024);
    constexpr int SM3 = narrow_smem(16, 8, 8, 1024);
    constexpr int SM4 = narrow_smem(8, 3, 16, 1024);
    constexpr int SMT = 3 * 8 * TTP * 4;

    cudaFuncSetAttribute(conv_wide<128, 64, 1, 256, true>,
                         cudaFuncAttributeMaxDynamicSharedMemorySize, SM0);
    cudaFuncSetAttribute(conv_wide<64, 32, 2, 512, true>,
                         cudaFuncAttributeMaxDynamicSharedMemorySize, SM1);
    cudaFuncSetAttribute(conv_wide<32, 16, 4, 1024, true>,
                         cudaFuncAttributeMaxDynamicSharedMemorySize, SM2);
    cudaFuncSetAttribute(conv_layer<16, 8, 8, 1024, 8, 8, true, false>,
                         cudaFuncAttributeMaxDynamicSharedMemorySize, SM3);
    cudaFuncSetAttribute(conv_layer<8, 3, 16, 1024, 3, 8, false, true>,
                         cudaFuncAttributeMaxDynamicSharedMemorySize, SM4);
    cudaFuncSetAttribute(transpose_loss,
                         cudaFuncAttributeMaxDynamicSharedMemorySize, SMT);

    prep_all<<<dim3(160, 6), 256>>>(w[0], w[1], w[2], w[3], w[4], wprep, accum, mask);

    conv_wide<128, 64, 1, 256, true>
        <<<dim3(1024 / 256, BATCH), 256, SM0>>>(x, wprep + o0, g[0], bb[0], mm[0], vv[0],
                                                bufA, 1024);
    conv_wide<64, 32, 2, 512, true>
        <<<dim3(2048 / 512, BATCH), 256, SM1>>>(bufA, wprep + o1, g[1], bb[1], mm[1], vv[1],
                                                bufB, 2048);
    conv_wide<32, 16, 4, 1024, true>
        <<<dim3(4096 / 1024, BATCH), 256, SM2>>>(bufB, wprep + o2, g[2], bb[2], mm[2], vv[2],
                                                 bufA, 4096);
    conv_layer<16, 8, 8, 1024, 8, 8, true, false>
        <<<dim3(8192 / 1024, BATCH), 256, SM3>>>(bufA, wprep + o3, g[3], bb[3], mm[3], vv[3],
                                                 nullptr, bufB, 8192);
    conv_layer<8, 3, 16, 1024, 3, 8, false, true>
        <<<dim3(16384 / 1024, BATCH), 256, SM4>>>(bufB, wprep + o4, nullptr, nullptr, nullptr,
                                                  nullptr, b_out, bufA, 16384);

    transpose_loss<<<dim3(NT_OUT / TT, 32), 256, SMT>>>(bufA, tg, (float*)d_out,
                                                        accum, mask);
    finalize_kernel<<<1, 1>>>(accum, mask, (float*)d_out, out_size);
}

// round 16
// speedup vs baseline: 1.2490x; 1.0211x over previous
#include <cuda_runtime.h>
#include <stdint.h>
#include <math.h>

#define BATCH 256
#define NT_OUT 32768
#define OUT_ELEMS (32u * 3u * 32768u * 8u)   // 25,165,824

__device__ float g_bufA[BATCH * 64 * 2048];
__device__ float g_bufB[BATCH * 64 * 2048];
__device__ float g_wprep[131072];
__device__ double g_loss_accum;
__device__ int    g_mask[BATCH];

typedef unsigned long long u64;

__device__ __forceinline__ void fma2(u64 &d, u64 a, u64 b) {
    asm("fma.rn.f32x2 %0, %1, %2, %0;" : "+l"(d) : "l"(a), "l"(b));
}
__device__ __forceinline__ u64 pack2(float lo, float hi) {
    u64 r; asm("mov.b64 %0, {%1, %2};" : "=l"(r) : "f"(lo), "f"(hi)); return r;
}
__device__ __forceinline__ void unpack2(u64 v, float &lo, float &hi) {
    asm("mov.b64 {%0, %1}, %2;" : "=f"(lo), "=f"(hi) : "l"(v));
}
__device__ __forceinline__ unsigned sm_u32(const void* p) {
    unsigned a;
    asm("{.reg .u64 t; cvta.to.shared.u64 t, %1; cvt.u32.u64 %0, t;}"
        : "=r"(a) : "l"(p));
    return a;
}

// X staging: ci-outer, j-strided, vector cp.async for interior, scalar at edges.
template<int CHUNK, int HALO, int HALOP, int G>
__device__ __forceinline__ void stage_x(float* Xd, const float* xb, size_t Lstride,
                                        int cc, int gbase, int L, int tid)
{
#pragma unroll 1
    for (int ci = 0; ci < CHUNK; ci++) {
        const float* src = xb + (size_t)(cc * CHUNK + ci) * Lstride;
        float* dst = Xd + ci * HALOP;
#pragma unroll 1
        for (int j = tid * G; j < HALO; j += 256 * G) {
            int gi = gbase + j;
            if (gi >= 0 && gi + G <= L && j + G <= HALO) {
                unsigned d = sm_u32(dst + j);
                if (G == 4)
                    asm volatile("cp.async.ca.shared.global [%0], [%1], 16;"
                                 :: "r"(d), "l"(src + gi));
                else
                    asm volatile("cp.async.ca.shared.global [%0], [%1], 8;"
                                 :: "r"(d), "l"(src + gi));
            } else {
#pragma unroll
                for (int e = 0; e < G; e++) {
                    if (j + e < HALO) {
                        int g = gbase + j + e;
                        if (g < 0) g = -g;
                        if (g >= L) g = 2 * L - 2 - g;
                        unsigned d = sm_u32(dst + j + e);
                        asm volatile("cp.async.ca.shared.global [%0], [%1], 4;"
                                     :: "r"(d), "l"(src + g));
                    }
                }
            }
        }
    }
}

// ---------------------------------------------------------------------------
// One prep kernel: all 5 layers' dup-pair weight reformat + accum/mask init.
// ---------------------------------------------------------------------------
__global__ void prep_all(const float* __restrict__ w0, const float* __restrict__ w1,
                         const float* __restrict__ w2, const float* __restrict__ w3,
                         const float* __restrict__ w4, float* __restrict__ wprep,
                         double* accum, int* mask)
{
    const int layer = blockIdx.y;
    if (layer == 5) {
        if (blockIdx.x == 0) {
            int t = threadIdx.x;
            if (t == 0) *accum = 0.0;
            if (t < BATCH) mask[t] = 0;
        }
        return;
    }
    const int CINs[5]   = {128, 64, 32, 16, 8};
    const int COUTs[5]  = {64, 32, 16, 8, 3};
    const int COUTPs[5] = {64, 32, 16, 8, 4};
    const int OFFs[5]   = {0, 81920, 102400, 107520, 108800};
    const float* W[5]   = {w0, w1, w2, w3, w4};
    const int CIN = CINs[layer], COUT = COUTs[layer], COUTP = COUTPs[layer];
    const int CHUNK = 8;
    const float* w = W[layer];
    float* dst = wprep + OFFs[layer];

    int n = COUT * CIN * 5;
    for (int idx = blockIdx.x * 256 + threadIdx.x; idx < n; idx += gridDim.x * 256) {
        int co = idx / (CIN * 5), r = idx - co * (CIN * 5);
        int ci = r / 5, k = r - ci * 5;
        int q = ci / CHUNK, cil = ci - q * CHUNK;
        float v = w[idx];
        int o = q * (CHUNK * 10 * COUTP) + (cil * 5 + k) * 2 * COUTP + 2 * co;
        dst[o] = v; dst[o + 1] = v;
    }
}

// ---------------------------------------------------------------------------
// WIDE conv (L0/L1/L2): RC=8 x RL=8. unroll-2 ci pipelining + spread edges.
// ---------------------------------------------------------------------------
template<int CIN, int COUT, int DIL, int TL, bool BN>
__global__ __launch_bounds__(256, 2)
void conv_wide(const float* __restrict__ x, const float* __restrict__ wp,
               const float* __restrict__ gg, const float* __restrict__ bb,
               const float* __restrict__ mm, const float* __restrict__ vv,
               float* __restrict__ y, int L)
{
    constexpr int RC = 8, CHUNK = 8;
    constexpr int PAD   = 2 * DIL;
    constexpr int HALO  = TL + 2 * PAD + 5;
    constexpr int HALOP = (HALO + 3) & ~3;
    constexpr int NPG   = TL / 8;
    constexpr int COUTP = COUT;
    constexpr int WCH   = CHUNK * 10 * COUTP;
    constexpr int NCH   = CIN / CHUNK;
    constexpr int WPC   = NPG / 32;
    constexpr int SFT   = PAD + 4;
    constexpr int G     = (DIL == 1) ? 2 : 4;

    const int tid  = threadIdx.x;
    const int tile = blockIdx.x;
    const int b    = blockIdx.y;
    const int pg   = tid % NPG;
    const int cg   = tid / NPG;
    const int lane = tid & 31;
    const int wic  = pg >> 5;
    const int lb   = pg * 8;
    const int cb   = cg * RC;

    extern __shared__ float sm[];
    float* Xbuf[2] = { sm, sm + CHUNK * HALOP };
    float* Wbuf[2] = { sm + 2 * CHUNK * HALOP, sm + 2 * CHUNK * HALOP + WCH };
    float* YsE   = sm + 2 * CHUNK * HALOP + 2 * WCH;   // [COUT][2]
    float* BndA3 = YsE + 2 * COUT;                     // [COUT][WPC]
    float* BndA0 = BndA3 + COUT * WPC;                 // [COUT][WPC]
    float* EdgeP = BndA0 + COUT * WPC;                 // [4*COUT] partials

    const float* xb    = x + (size_t)b * CIN * L;
    const int    gbase = tile * TL - SFT;

    u64 acc[RC][4];
#pragma unroll
    for (int q = 0; q < RC; q++)
#pragma unroll
        for (int j = 0; j < 4; j++) acc[q][j] = 0ull;

    // spread edge accumulation: tid < 4*COUT, half the ci range each
    float eacc = 0.f;
    const int eIdx  = tid >> 2;
    const int eSide = (tid >> 1) & 1;
    const int eHalf = tid & 1;
    int ej = 0;
    if (tid < 4 * COUT) {
        int gl = tile * TL + (eSide ? TL : -1);
        if (gl < 0)  gl = 0;
        if (gl >= L) gl = L - 1;
        ej = gl - tile * TL;
    }

    auto stage = [&](int p, int cc) {
        stage_x<CHUNK, HALO, HALOP, G>(Xbuf[p], xb, L, cc, gbase, L, tid);
        const float4* wsrc = (const float4*)(wp + (size_t)cc * WCH);
        float* Wd = Wbuf[p];
        for (int idx = tid; idx < WCH / 4; idx += 256) {
            unsigned d = sm_u32(Wd + idx * 4);
            asm volatile("cp.async.cg.shared.global [%0], [%1], 16;"
                         :: "r"(d), "l"(wsrc + idx));
        }
        asm volatile("cp.async.commit_group;");
    };

    stage(0, 0);

    for (int cc = 0; cc < NCH; cc++) {
        const int p = cc & 1;
        asm volatile("cp.async.wait_group 0;");
        __syncthreads();
        if (cc + 1 < NCH) stage(p ^ 1, cc + 1);

        const float* Xs = Xbuf[p];
        const float* Ws = Wbuf[p];

#pragma unroll 2
        for (int ci = 0; ci < CHUNK; ci++) {
            const float* xr = Xs + ci * HALOP + lb + 4;
            if (DIL == 1) {
                float4 F0 = *(const float4*)xr;
                float4 F1 = *(const float4*)(xr + 4);
                float4 F2 = *(const float4*)(xr + 8);
                float f[12] = {F0.x, F0.y, F0.z, F0.w, F1.x, F1.y, F1.z, F1.w,
                               F2.x, F2.y, F2.z, F2.w};
#pragma unroll
                for (int k = 0; k < 5; k++) {
                    u64 xp[4];
#pragma unroll
                    for (int j = 0; j < 4; j++)
                        xp[j] = pack2(f[k + 2 * j], f[k + 2 * j + 1]);
                    const float* wr = Ws + (ci * 5 + k) * 2 * COUTP + 2 * cb;
#pragma unroll
                    for (int qq = 0; qq < 4; qq++) {
                        ulonglong2 wv = *(const ulonglong2*)(wr + 4 * qq);
#pragma unroll
                        for (int j = 0; j < 4; j++) {
                            fma2(acc[2 * qq][j], wv.x, xp[j]);
                            fma2(acc[2 * qq + 1][j], wv.y, xp[j]);
                        }
                    }
                }
            } else if (DIL == 2) {
                u64 S[8];
#pragma unroll
                for (int i = 0; i < 4; i++) {
                    ulonglong2 u = *(const ulonglong2*)(xr + 4 * i);
                    S[2 * i] = u.x; S[2 * i + 1] = u.y;
                }
#pragma unroll
                for (int k = 0; k < 5; k++) {
                    const float* wr = Ws + (ci * 5 + k) * 2 * COUTP + 2 * cb;
#pragma unroll
                    for (int qq = 0; qq < 4; qq++) {
                        ulonglong2 wv = *(const ulonglong2*)(wr + 4 * qq);
#pragma unroll
                        for (int j = 0; j < 4; j++) {
                            fma2(acc[2 * qq][j], wv.x, S[k + j]);
                            fma2(acc[2 * qq + 1][j], wv.y, S[k + j]);
                        }
                    }
                }
            } else {  // DIL == 4: per-k aligned loads (low register pressure)
#pragma unroll
                for (int k = 0; k < 5; k++) {
                    ulonglong2 xa = *(const ulonglong2*)(xr + 4 * k);
                    ulonglong2 xc = *(const ulonglong2*)(xr + 4 * k + 4);
                    u64 xp[4] = {xa.x, xa.y, xc.x, xc.y};
                    const float* wr = Ws + (ci * 5 + k) * 2 * COUTP + 2 * cb;
#pragma unroll
                    for (int qq = 0; qq < 4; qq++) {
                        ulonglong2 wv = *(const ulonglong2*)(wr + 4 * qq);
#pragma unroll
                        for (int j = 0; j < 4; j++) {
                            fma2(acc[2 * qq][j], wv.x, xp[j]);
                            fma2(acc[2 * qq + 1][j], wv.y, xp[j]);
                        }
                    }
                }
            }
        }

        if (tid < 4 * COUT) {
#pragma unroll 1
            for (int ci = eHalf * (CHUNK / 2); ci < (eHalf + 1) * (CHUNK / 2); ci++)
#pragma unroll
                for (int k = 0; k < 5; k++)
                    eacc = fmaf(Ws[(ci * 5 + k) * 2 * COUTP + 2 * eIdx],
                                Xs[ci * HALOP + ej + 4 + k * DIL], eacc);
        }
    }

    // publish edge partials, then combine under BN
    if (tid < 4 * COUT) EdgeP[tid] = eacc;
    __syncthreads();

    float v[RC][8];
#pragma unroll
    for (int q = 0; q < RC; q++) {
        int c = cb + q;
        float inv = gg[c] * rsqrtf(vv[c] + 1e-5f);
        float sh  = bb[c] - mm[c] * inv;
#pragma unroll
        for (int j = 0; j < 4; j++) {
            float a0, a1;
            unpack2(acc[q][j], a0, a1);
            a0 = a0 * inv + sh; a1 = a1 * inv + sh;
            if (BN) { a0 = fmaxf(a0, 0.f); a1 = fmaxf(a1, 0.f); }
            v[q][2 * j] = a0; v[q][2 * j + 1] = a1;
        }
        if (lane == 31) BndA3[c * WPC + wic] = v[q][7];
        if (lane == 0)  BndA0[c * WPC + wic] = v[q][0];
    }
    if (tid < 2 * COUT) {
        int c = tid >> 1, side = tid & 1;
        float inv = gg[c] * rsqrtf(vv[c] + 1e-5f);
        float e = EdgeP[4 * c + 2 * side] + EdgeP[4 * c + 2 * side + 1];
        float val = e * inv + bb[c] - mm[c] * inv;
        if (BN) val = fmaxf(val, 0.f);
        YsE[2 * c + side] = val;
    }
    __syncthreads();

    const int Lup = 2 * L;
#pragma unroll
    for (int q = 0; q < RC; q++) {
        int c = cb + q;
        float yl = __shfl_up_sync(0xffffffffu, v[q][7], 1);
        float yr = __shfl_down_sync(0xffffffffu, v[q][0], 1);
        if (lane == 0)  yl = (wic == 0)       ? YsE[2 * c]     : BndA3[c * WPC + wic - 1];
        if (lane == 31) yr = (wic == WPC - 1) ? YsE[2 * c + 1] : BndA0[c * WPC + wic + 1];
        float o[16];
        o[0] = 0.25f * yl + 0.75f * v[q][0];
#pragma unroll
        for (int j = 1; j < 8; j++) o[2 * j] = 0.25f * v[q][j - 1] + 0.75f * v[q][j];
#pragma unroll
        for (int j = 0; j < 7; j++) o[2 * j + 1] = 0.75f * v[q][j] + 0.25f * v[q][j + 1];
        o[15] = 0.75f * v[q][7] + 0.25f * yr;
        size_t off = ((size_t)b * COUT + c) * Lup + 2 * (tile * TL + lb);
#pragma unroll
        for (int i = 0; i < 4; i++)
            *(float4*)(y + off + 4 * i) =
                make_float4(o[4 * i], o[4 * i + 1], o[4 * i + 2], o[4 * i + 3]);
    }
}

// ---------------------------------------------------------------------------
// Narrow conv (L3/L4): R9-proven RC x4 config.
// ---------------------------------------------------------------------------
template<int CIN, int COUT, int DIL, int TL, int RC, int CHUNK, bool BN, bool FINAL>
__global__ __launch_bounds__(256, 3)
void conv_layer(const float* __restrict__ x, const float* __restrict__ wp,
                const float* __restrict__ gg, const float* __restrict__ bb,
                const float* __restrict__ mm, const float* __restrict__ vv,
                const float* __restrict__ bout, float* __restrict__ y, int L)
{
    constexpr int PAD   = 2 * DIL;
    constexpr int SFT   = PAD + 4;
    constexpr int HALO  = TL + 2 * PAD + 5;
    constexpr int HALOP = (HALO + 3) & ~3;
    constexpr int NPG   = TL / 4;
    constexpr int COUTP = (COUT + 3) & ~3;
    constexpr int NQ    = (RC + 1) / 2;
    constexpr int WCH   = CHUNK * 10 * COUTP;
    constexpr int NCH   = CIN / CHUNK;
    constexpr int WPC   = NPG / 32;

    const int tid  = threadIdx.x;
    const int tile = blockIdx.x;
    const int b    = blockIdx.y;
    const int pg   = tid % NPG;
    const int cg   = tid / NPG;
    const int lane = tid & 31;
    const int wic  = pg >> 5;
    const int lb   = pg * 4;
    const int cb   = cg * RC;

    extern __shared__ float sm[];
    float* Xbuf[2] = { sm, sm + CHUNK * HALOP };
    float* Wbuf[2] = { sm + 2 * CHUNK * HALOP, sm + 2 * CHUNK * HALOP + WCH };
    float* YsE   = sm + 2 * CHUNK * HALOP + 2 * WCH;
    float* BndA3 = YsE + 2 * COUT;
    float* BndA0 = BndA3 + COUT * WPC;

    const float* xb    = x + (size_t)b * CIN * L;
    const int    gbase = tile * TL - SFT;

    u64 acc[RC][2];
#pragma unroll
    for (int q = 0; q < RC; q++) { acc[q][0] = 0ull; acc[q][1] = 0ull; }

    float eacc = 0.f;
    const int eIdx = tid >> 1, eSide = tid & 1;
    int ej = 0;
    if (tid < 2 * COUT) {
        int gl = tile * TL + (eSide ? TL : -1);
        if (gl < 0)  gl = 0;
        if (gl >= L) gl = L - 1;
        ej = gl - tile * TL;
    }

    auto stage = [&](int p, int cc) {
        stage_x<CHUNK, HALO, HALOP, 4>(Xbuf[p], xb, L, cc, gbase, L, tid);
        const float4* wsrc = (const float4*)(wp + (size_t)cc * WCH);
        float* Wd = Wbuf[p];
        for (int idx = tid; idx < WCH / 4; idx += 256) {
            unsigned d = sm_u32(Wd + idx * 4);
            asm volatile("cp.async.cg.shared.global [%0], [%1], 16;"
                         :: "r"(d), "l"(wsrc + idx));
        }
        asm volatile("cp.async.commit_group;");
    };

    stage(0, 0);

    for (int cc = 0; cc < NCH; cc++) {
        const int p = cc & 1;
        asm volatile("cp.async.wait_group 0;");
        __syncthreads();
        if (cc + 1 < NCH) stage(p ^ 1, cc + 1);

        const float* Xs = Xbuf[p];
        const float* Ws = Wbuf[p];

#pragma unroll 2
        for (int ci = 0; ci < CHUNK; ci++) {
            const float* xr = Xs + ci * HALOP + lb + 4;
#pragma unroll
            for (int k = 0; k < 5; k++) {
                ulonglong2 xv = *(const ulonglong2*)(xr + k * DIL);
                u64 xp0 = xv.x, xp1 = xv.y;
                const float* wr = Ws + (ci * 5 + k) * 2 * COUTP + 2 * cb;
#pragma unroll
                for (int qq = 0; qq < NQ; qq++) {
                    ulonglong2 wv = *(const ulonglong2*)(wr + 4 * qq);
                    fma2(acc[2 * qq][0], wv.x, xp0);
                    fma2(acc[2 * qq][1], wv.x, xp1);
                    if (2 * qq + 1 < RC) {
                        fma2(acc[2 * qq + 1][0], wv.y, xp0);
                        fma2(acc[2 * qq + 1][1], wv.y, xp1);
                    }
                }
            }
        }

        if (tid < 2 * COUT) {
#pragma unroll 1
            for (int ci = 0; ci < CHUNK; ci++)
#pragma unroll
                for (int k = 0; k < 5; k++)
                    eacc = fmaf(Ws[(ci * 5 + k) * 2 * COUTP + 2 * eIdx],
                                Xs[ci * HALOP + ej + 4 + k * DIL], eacc);
        }
    }

    float v[RC][4];
#pragma unroll
    for (int q = 0; q < RC; q++) {
        int c = cb + q;
        float sc, sh;
        if (FINAL) { sc = 1.f; sh = bout[c]; }
        else {
            float inv = gg[c] * rsqrtf(vv[c] + 1e-5f);
            sc = inv; sh = bb[c] - mm[c] * inv;
        }
        float a0, a1, a2, a3;
        unpack2(acc[q][0], a0, a1);
        unpack2(acc[q][1], a2, a3);
        a0 = a0 * sc + sh; a1 = a1 * sc + sh;
        a2 = a2 * sc + sh; a3 = a3 * sc + sh;
        if (BN) {
            a0 = fmaxf(a0, 0.f); a1 = fmaxf(a1, 0.f);
            a2 = fmaxf(a2, 0.f); a3 = fmaxf(a3, 0.f);
        }
        v[q][0] = a0; v[q][1] = a1; v[q][2] = a2; v[q][3] = a3;
        if (lane == 31) BndA3[c * WPC + wic] = a3;
        if (lane == 0)  BndA0[c * WPC + wic] = a0;
    }
    if (tid < 2 * COUT) {
        int c = eIdx;
        float sc, sh;
        if (FINAL) { sc = 1.f; sh = bout[c]; }
        else {
            float inv = gg[c] * rsqrtf(vv[c] + 1e-5f);
            sc = inv; sh = bb[c] - mm[c] * inv;
        }
        float val = eacc * sc + sh;
        if (BN) val = fmaxf(val, 0.f);
        YsE[2 * c + eSide] = val;
    }
    __syncthreads();

    const int Lup = 2 * L;
#pragma unroll
    for (int q = 0; q < RC; q++) {
        int c = cb + q;
        float yl = __shfl_up_sync(0xffffffffu, v[q][3], 1);
        float yr = __shfl_down_sync(0xffffffffu, v[q][0], 1);
        if (lane == 0)  yl = (wic == 0)       ? YsE[2 * c]     : BndA3[c * WPC + wic - 1];
        if (lane == 31) yr = (wic == WPC - 1) ? YsE[2 * c + 1] : BndA0[c * WPC + wic + 1];
        float y0 = v[q][0], y1 = v[q][1], y2 = v[q][2], y3 = v[q][3];
        float o0 = 0.25f * yl + 0.75f * y0, o1 = 0.75f * y0 + 0.25f * y1;
        float o2 = 0.25f * y0 + 0.75f * y1, o3 = 0.75f * y1 + 0.25f * y2;
        float o4 = 0.25f * y1 + 0.75f * y2, o5 = 0.75f * y2 + 0.25f * y3;
        float o6 = 0.25f * y2 + 0.75f * y3, o7 = 0.75f * y3 + 0.25f * yr;
        size_t off = ((size_t)b * COUT + c) * Lup + 2 * (tile * TL + lb);
        *(float4*)(y + off)     = make_float4(o0, o1, o2, o3);
        *(float4*)(y + off + 4) = make_float4(o4, o5, o6, o7);
    }
}

// ---------------------------------------------------------------------------
#define TT 512
#define TTP 516
__global__ __launch_bounds__(256)
void transpose_loss(const float* __restrict__ in, const float* __restrict__ tg,
                    float* __restrict__ out, double* accum, int* mask)
{
    const int bt = blockIdx.y;
    const int t0 = blockIdx.x * TT;
    const int tid = threadIdx.x;
    extern __shared__ float tile[];

    for (int idx = tid; idx < 3 * 8 * TT; idx += 256) {
        int c = idx / (8 * TT), r = idx - c * (8 * TT);
        int st = r / TT, t = r - st * TT;
        tile[(c * 8 + st) * TTP + t] =
            in[((size_t)(bt * 8 + st) * 3 + c) * NT_OUT + t0 + t];
    }
    __syncthreads();

    float s = 0.f;
    bool nz = false;
    const size_t ob = ((size_t)bt * 3) * NT_OUT * 8 + (size_t)t0 * 8;
    const size_t cs = (size_t)NT_OUT * 8;
#pragma unroll 4
    for (int i = 0; i < (TT * 8) / 256; i++) {
        int f = i * 256 + tid;
        int t = f >> 3, st = f & 7;
        float o0 = tile[(0 * 8 + st) * TTP + t];
        float o1 = tile[(1 * 8 + st) * TTP + t];
        float o2 = tile[(2 * 8 + st) * TTP + t];
        out[ob + f]          = o0;
        out[ob + cs + f]     = o1;
        out[ob + 2 * cs + f] = o2;
        float t0v = tg[ob + f], t1v = tg[ob + cs + f], t2v = tg[ob + 2 * cs + f];
        float mx  = fmaxf(o0, fmaxf(o1, o2));
        float lse = mx + __logf(__expf(o0 - mx) + __expf(o1 - mx) + __expf(o2 - mx));
        s += t0v * (lse - o0) + t1v * (lse - o1) + t2v * (lse - o2);
        nz = nz || (t0v != 0.f) || (t1v != 0.f) || (t2v != 0.f);
    }
    if (nz) atomicOr(&mask[bt * 8 + (tid & 7)], 1);

    __shared__ float red[256];
    red[tid] = s;
    __syncthreads();
    for (int o = 128; o > 0; o >>= 1) {
        if (tid < o) red[tid] += red[tid + o];
        __syncthreads();
    }
    if (tid == 0) atomicAdd(accum, (double)red[0]);
}

__global__ void finalize_kernel(const double* accum, const int* mask,
                                float* out, int out_size)
{
    if (threadIdx.x != 0 || blockIdx.x != 0) return;
    int num = 0;
    for (int i = 0; i < BATCH; i++) num += (mask[i] ? 1 : 0);
    double loss = *accum / ((double)num * (double)NT_OUT);
    if ((unsigned)out_size > OUT_ELEMS) out[OUT_ELEMS] = (float)loss;
}

// ---------------------------------------------------------------------------
static constexpr int wide_smem(int CIN, int COUT, int DIL, int TL) {
    int halop = ((TL + 4 * DIL + 5) + 3) & ~3;
    int wpc = (TL / 8) / 32;
    return (2 * 8 * halop + 2 * 8 * 10 * COUT + 2 * COUT + 2 * COUT * wpc
            + 4 * COUT) * 4;
}
static constexpr int narrow_smem(int CIN, int COUT, int DIL, int TL) {
    int halop = ((TL + 4 * DIL + 5) + 3) & ~3;
    int coutp = (COUT + 3) & ~3;
    int wpc = (TL / 4) / 32;
    return (2 * 8 * halop + 2 * 8 * 10 * coutp + 2 * COUT + 2 * COUT * wpc) * 4;
}

extern "C" void kernel_launch(void* const* d_in, const int* in_sizes, int n_in,
                              void* d_out, int out_size)
{
    const float* x  = (const float*)d_in[0];
    const float* tg = (const float*)d_in[1];
    const float *w[5], *g[4], *bb[4], *mm[4], *vv[4], *b_out;

    bool inter = (n_in > 3) && (in_sizes[3] == 64);
    if (inter) {
        for (int i = 0; i < 4; i++) {
            w[i]  = (const float*)d_in[2 + 5 * i];
            g[i]  = (const float*)d_in[3 + 5 * i];
            bb[i] = (const float*)d_in[4 + 5 * i];
            mm[i] = (const float*)d_in[5 + 5 * i];
            vv[i] = (const float*)d_in[6 + 5 * i];
        }
    } else {
        for (int i = 0; i < 4; i++) {
            w[i]  = (const float*)d_in[2 + i];
            g[i]  = (const float*)d_in[6 + i];
            bb[i] = (const float*)d_in[10 + i];
            mm[i] = (const float*)d_in[14 + i];
            vv[i] = (const float*)d_in[18 + i];
        }
    }
    w[4]  = (const float*)d_in[22];
    b_out = (const float*)d_in[23];

    float *bufA, *bufB, *wprep;
    double* accum;
    int* mask;
    cudaGetSymbolAddress((void**)&bufA, g_bufA);
    cudaGetSymbolAddress((void**)&bufB, g_bufB);
    cudaGetSymbolAddress((void**)&wprep, g_wprep);
    cudaGetSymbolAddress((void**)&accum, g_loss_accum);
    cudaGetSymbolAddress((void**)&mask, g_mask);

    const size_t o0 = 0, o1 = 81920, o2 = 102400, o3 = 107520, o4 = 108800;

    constexpr int SM0 = wide_smem(128, 64, 1, 256);
    constexpr int SM1 = wide_smem(64, 32, 2, 512);
    constexpr int SM2 = wide_smem(32, 16, 4, 1024);
    constexpr int SM3 = narrow_smem(16, 8, 8, 1024);
    constexpr int SM4 = narrow_smem(8, 3, 16, 1024);
    constexpr int SMT = 3 * 8 * TTP * 4;

    cudaFuncSetAttribute(conv_wide<128, 64, 1, 256, true>,
                         cudaFuncAttributeMaxDynamicSharedMemorySize, SM0);
    cudaFuncSetAttribute(conv_wide<64, 32, 2, 512, true>,
                         cudaFuncAttributeMaxDynamicSharedMemorySize, SM1);
    cudaFuncSetAttribute(conv_wide<32, 16, 4, 1024, true>,
                         cudaFuncAttributeMaxDynamicSharedMemorySize, SM2);
    cudaFuncSetAttribute(conv_layer<16, 8, 8, 1024, 8, 8, true, false>,
                         cudaFuncAttributeMaxDynamicSharedMemorySize, SM3);
    cudaFuncSetAttribute(conv_layer<8, 3, 16, 1024, 3, 8, false, true>,
                         cudaFuncAttributeMaxDynamicSharedMemorySize, SM4);
    cudaFuncSetAttribute(transpose_loss,
                         cudaFuncAttributeMaxDynamicSharedMemorySize, SMT);

    prep_all<<<dim3(160, 6), 256>>>(w[0], w[1], w[2], w[3], w[4], wprep, accum, mask);

    conv_wide<128, 64, 1, 256, true>
        <<<dim3(1024 / 256, BATCH), 256, SM0>>>(x, wprep + o0, g[0], bb[0], mm[0], vv[0],
                                                bufA, 1024);
    conv_wide<64, 32, 2, 512, true>
        <<<dim3(2048 / 512, BATCH), 256, SM1>>>(bufA, wprep + o1, g[1], bb[1], mm[1], vv[1],
                                                bufB, 2048);
    conv_wide<32, 16, 4, 1024, true>
        <<<dim3(4096 / 1024, BATCH), 256, SM2>>>(bufB, wprep + o2, g[2], bb[2], mm[2], vv[2],
                                                 bufA, 4096);
    conv_layer<16, 8, 8, 1024, 8, 8, true, false>
        <<<dim3(8192 / 1024, BATCH), 256, SM3>>>(bufA, wprep + o3, g[3], bb[3], mm[3], vv[3],
                                                 nullptr, bufB, 8192);
    conv_layer<8, 3, 16, 1024, 3, 8, false, true>
        <<<dim3(16384 / 1024, BATCH), 256, SM4>>>(bufB, wprep + o4, nullptr, nullptr, nullptr,
                                                  nullptr, b_out, bufA, 16384);

    transpose_loss<<<dim3(NT_OUT / TT, 32), 256, SMT>>>(bufA, tg, (float*)d_out,
                                                        accum, mask);
    finalize_kernel<<<1, 1>>>(accum, mask, (float*)d_out, out_size);
}

// round 17
// speedup vs baseline: 1.2586x; 1.0077x over previous
#include <cuda_runtime.h>
#include <stdint.h>
#include <math.h>

#define BATCH 256
#define NT_OUT 32768
#define OUT_ELEMS (32u * 3u * 32768u * 8u)   // 25,165,824

__device__ float g_bufA[BATCH * 64 * 2048];
__device__ float g_bufB[BATCH * 64 * 2048];
__device__ float g_wprep[131072];
__device__ double g_loss_accum;
__device__ int    g_mask[BATCH];

typedef unsigned long long u64;

__device__ __forceinline__ void fma2(u64 &d, u64 a, u64 b) {
    asm("fma.rn.f32x2 %0, %1, %2, %0;" : "+l"(d) : "l"(a), "l"(b));
}
__device__ __forceinline__ u64 pack2(float lo, float hi) {
    u64 r; asm("mov.b64 %0, {%1, %2};" : "=l"(r) : "f"(lo), "f"(hi)); return r;
}
__device__ __forceinline__ void unpack2(u64 v, float &lo, float &hi) {
    asm("mov.b64 {%0, %1}, %2;" : "=f"(lo), "=f"(hi) : "l"(v));
}
__device__ __forceinline__ unsigned sm_u32(const void* p) {
    unsigned a;
    asm("{.reg .u64 t; cvta.to.shared.u64 t, %1; cvt.u32.u64 %0, t;}"
        : "=r"(a) : "l"(p));
    return a;
}

// X staging: ci-outer, j-strided, vector cp.async for interior, scalar at edges.
template<int CHUNK, int HALO, int HALOP, int G>
__device__ __forceinline__ void stage_x(float* Xd, const float* xb, size_t Lstride,
                                        int cc, int gbase, int L, int tid)
{
#pragma unroll 1
    for (int ci = 0; ci < CHUNK; ci++) {
        const float* src = xb + (size_t)(cc * CHUNK + ci) * Lstride;
        float* dst = Xd + ci * HALOP;
#pragma unroll 1
        for (int j = tid * G; j < HALO; j += 256 * G) {
            int gi = gbase + j;
            if (gi >= 0 && gi + G <= L && j + G <= HALO) {
                unsigned d = sm_u32(dst + j);
                if (G == 4)
                    asm volatile("cp.async.ca.shared.global [%0], [%1], 16;"
                                 :: "r"(d), "l"(src + gi));
                else
                    asm volatile("cp.async.ca.shared.global [%0], [%1], 8;"
                                 :: "r"(d), "l"(src + gi));
            } else {
#pragma unroll
                for (int e = 0; e < G; e++) {
                    if (j + e < HALO) {
                        int g = gbase + j + e;
                        if (g < 0) g = -g;
                        if (g >= L) g = 2 * L - 2 - g;
                        unsigned d = sm_u32(dst + j + e);
                        asm volatile("cp.async.ca.shared.global [%0], [%1], 4;"
                                     :: "r"(d), "l"(src + g));
                    }
                }
            }
        }
    }
}

// ---------------------------------------------------------------------------
// One prep kernel: all 5 layers' dup-pair weight reformat + accum/mask init.
// ---------------------------------------------------------------------------
__global__ void prep_all(const float* __restrict__ w0, const float* __restrict__ w1,
                         const float* __restrict__ w2, const float* __restrict__ w3,
                         const float* __restrict__ w4, float* __restrict__ wprep,
                         double* accum, int* mask)
{
    const int layer = blockIdx.y;
    if (layer == 5) {
        if (blockIdx.x == 0) {
            int t = threadIdx.x;
            if (t == 0) *accum = 0.0;
            if (t < BATCH) mask[t] = 0;
        }
        return;
    }
    const int CINs[5]   = {128, 64, 32, 16, 8};
    const int COUTs[5]  = {64, 32, 16, 8, 3};
    const int COUTPs[5] = {64, 32, 16, 8, 4};
    const int OFFs[5]   = {0, 81920, 102400, 107520, 108800};
    const float* W[5]   = {w0, w1, w2, w3, w4};
    const int CIN = CINs[layer], COUT = COUTs[layer], COUTP = COUTPs[layer];
    const int CHUNK = 8;
    const float* w = W[layer];
    float* dst = wprep + OFFs[layer];

    int n = COUT * CIN * 5;
    for (int idx = blockIdx.x * 256 + threadIdx.x; idx < n; idx += gridDim.x * 256) {
        int co = idx / (CIN * 5), r = idx - co * (CIN * 5);
        int ci = r / 5, k = r - ci * 5;
        int q = ci / CHUNK, cil = ci - q * CHUNK;
        float v = w[idx];
        int o = q * (CHUNK * 10 * COUTP) + (cil * 5 + k) * 2 * COUTP + 2 * co;
        dst[o] = v; dst[o + 1] = v;
    }
}

// ---------------------------------------------------------------------------
// WIDE conv (L0/L1/L2): RC=8 x RL=8. Per-DIL unroll policy + spread edges.
// ---------------------------------------------------------------------------
template<int CIN, int COUT, int DIL, int TL, bool BN>
__global__ __launch_bounds__(256, 2)
void conv_wide(const float* __restrict__ x, const float* __restrict__ wp,
               const float* __restrict__ gg, const float* __restrict__ bb,
               const float* __restrict__ mm, const float* __restrict__ vv,
               float* __restrict__ y, int L)
{
    constexpr int RC = 8, CHUNK = 8;
    constexpr int PAD   = 2 * DIL;
    constexpr int HALO  = TL + 2 * PAD + 5;
    constexpr int HALOP = (HALO + 3) & ~3;
    constexpr int NPG   = TL / 8;
    constexpr int COUTP = COUT;
    constexpr int WCH   = CHUNK * 10 * COUTP;
    constexpr int NCH   = CIN / CHUNK;
    constexpr int WPC   = NPG / 32;
    constexpr int SFT   = PAD + 4;
    constexpr int G     = (DIL == 1) ? 2 : 4;

    const int tid  = threadIdx.x;
    const int tile = blockIdx.x;
    const int b    = blockIdx.y;
    const int pg   = tid % NPG;
    const int cg   = tid / NPG;
    const int lane = tid & 31;
    const int wic  = pg >> 5;
    const int lb   = pg * 8;
    const int cb   = cg * RC;

    extern __shared__ float sm[];
    float* Xbuf[2] = { sm, sm + CHUNK * HALOP };
    float* Wbuf[2] = { sm + 2 * CHUNK * HALOP, sm + 2 * CHUNK * HALOP + WCH };
    float* YsE   = sm + 2 * CHUNK * HALOP + 2 * WCH;   // [COUT][2]
    float* BndA3 = YsE + 2 * COUT;                     // [COUT][WPC]
    float* BndA0 = BndA3 + COUT * WPC;                 // [COUT][WPC]
    float* EdgeP = BndA0 + COUT * WPC;                 // [4*COUT] partials

    const float* xb    = x + (size_t)b * CIN * L;
    const int    gbase = tile * TL - SFT;

    u64 acc[RC][4];
#pragma unroll
    for (int q = 0; q < RC; q++)
#pragma unroll
        for (int j = 0; j < 4; j++) acc[q][j] = 0ull;

    float eacc = 0.f;
    const int eIdx  = tid >> 2;
    const int eSide = (tid >> 1) & 1;
    const int eHalf = tid & 1;
    int ej = 0;
    if (tid < 4 * COUT) {
        int gl = tile * TL + (eSide ? TL : -1);
        if (gl < 0)  gl = 0;
        if (gl >= L) gl = L - 1;
        ej = gl - tile * TL;
    }

    auto stage = [&](int p, int cc) {
        stage_x<CHUNK, HALO, HALOP, G>(Xbuf[p], xb, L, cc, gbase, L, tid);
        const float4* wsrc = (const float4*)(wp + (size_t)cc * WCH);
        float* Wd = Wbuf[p];
        for (int idx = tid; idx < WCH / 4; idx += 256) {
            unsigned d = sm_u32(Wd + idx * 4);
            asm volatile("cp.async.cg.shared.global [%0], [%1], 16;"
                         :: "r"(d), "l"(wsrc + idx));
        }
        asm volatile("cp.async.commit_group;");
    };

    stage(0, 0);

    for (int cc = 0; cc < NCH; cc++) {
        const int p = cc & 1;
        asm volatile("cp.async.wait_group 0;");
        __syncthreads();
        if (cc + 1 < NCH) stage(p ^ 1, cc + 1);

        const float* Xs = Xbuf[p];
        const float* Ws = Wbuf[p];

        if (DIL == 4) {
            // unroll 1: keep per-k LDS stream shallow (crossbar-friendly)
#pragma unroll 1
            for (int ci = 0; ci < CHUNK; ci++) {
                const float* xr = Xs + ci * HALOP + lb + 4;
#pragma unroll
                for (int k = 0; k < 5; k++) {
                    ulonglong2 xa = *(const ulonglong2*)(xr + 4 * k);
                    ulonglong2 xc = *(const ulonglong2*)(xr + 4 * k + 4);
                    u64 xp[4] = {xa.x, xa.y, xc.x, xc.y};
                    const float* wr = Ws + (ci * 5 + k) * 2 * COUTP + 2 * cb;
#pragma unroll
                    for (int qq = 0; qq < 4; qq++) {
                        ulonglong2 wv = *(const ulonglong2*)(wr + 4 * qq);
#pragma unroll
                        for (int j = 0; j < 4; j++) {
                            fma2(acc[2 * qq][j], wv.x, xp[j]);
                            fma2(acc[2 * qq + 1][j], wv.y, xp[j]);
                        }
                    }
                }
            }
        } else {
#pragma unroll 2
            for (int ci = 0; ci < CHUNK; ci++) {
                const float* xr = Xs + ci * HALOP + lb + 4;
                if (DIL == 1) {
                    float4 F0 = *(const float4*)xr;
                    float4 F1 = *(const float4*)(xr + 4);
                    float4 F2 = *(const float4*)(xr + 8);
                    float f[12] = {F0.x, F0.y, F0.z, F0.w, F1.x, F1.y, F1.z, F1.w,
                                   F2.x, F2.y, F2.z, F2.w};
#pragma unroll
                    for (int k = 0; k < 5; k++) {
                        u64 xp[4];
#pragma unroll
                        for (int j = 0; j < 4; j++)
                            xp[j] = pack2(f[k + 2 * j], f[k + 2 * j + 1]);
                        const float* wr = Ws + (ci * 5 + k) * 2 * COUTP + 2 * cb;
#pragma unroll
                        for (int qq = 0; qq < 4; qq++) {
                            ulonglong2 wv = *(const ulonglong2*)(wr + 4 * qq);
#pragma unroll
                            for (int j = 0; j < 4; j++) {
                                fma2(acc[2 * qq][j], wv.x, xp[j]);
                                fma2(acc[2 * qq + 1][j], wv.y, xp[j]);
                            }
                        }
                    }
                } else {  // DIL == 2
                    u64 S[8];
#pragma unroll
                    for (int i = 0; i < 4; i++) {
                        ulonglong2 u = *(const ulonglong2*)(xr + 4 * i);
                        S[2 * i] = u.x; S[2 * i + 1] = u.y;
                    }
#pragma unroll
                    for (int k = 0; k < 5; k++) {
                        const float* wr = Ws + (ci * 5 + k) * 2 * COUTP + 2 * cb;
#pragma unroll
                        for (int qq = 0; qq < 4; qq++) {
                            ulonglong2 wv = *(const ulonglong2*)(wr + 4 * qq);
#pragma unroll
                            for (int j = 0; j < 4; j++) {
                                fma2(acc[2 * qq][j], wv.x, S[k + j]);
                                fma2(acc[2 * qq + 1][j], wv.y, S[k + j]);
                            }
                        }
                    }
                }
            }
        }

        if (tid < 4 * COUT) {
#pragma unroll 1
            for (int ci = eHalf * (CHUNK / 2); ci < (eHalf + 1) * (CHUNK / 2); ci++)
#pragma unroll
                for (int k = 0; k < 5; k++)
                    eacc = fmaf(Ws[(ci * 5 + k) * 2 * COUTP + 2 * eIdx],
                                Xs[ci * HALOP + ej + 4 + k * DIL], eacc);
        }
    }

    if (tid < 4 * COUT) EdgeP[tid] = eacc;
    __syncthreads();

    float v[RC][8];
#pragma unroll
    for (int q = 0; q < RC; q++) {
        int c = cb + q;
        float inv = gg[c] * rsqrtf(vv[c] + 1e-5f);
        float sh  = bb[c] - mm[c] * inv;
#pragma unroll
        for (int j = 0; j < 4; j++) {
            float a0, a1;
            unpack2(acc[q][j], a0, a1);
            a0 = a0 * inv + sh; a1 = a1 * inv + sh;
            if (BN) { a0 = fmaxf(a0, 0.f); a1 = fmaxf(a1, 0.f); }
            v[q][2 * j] = a0; v[q][2 * j + 1] = a1;
        }
        if (lane == 31) BndA3[c * WPC + wic] = v[q][7];
        if (lane == 0)  BndA0[c * WPC + wic] = v[q][0];
    }
    if (tid < 2 * COUT) {
        int c = tid >> 1, side = tid & 1;
        float inv = gg[c] * rsqrtf(vv[c] + 1e-5f);
        float e = EdgeP[4 * c + 2 * side] + EdgeP[4 * c + 2 * side + 1];
        float val = e * inv + bb[c] - mm[c] * inv;
        if (BN) val = fmaxf(val, 0.f);
        YsE[2 * c + side] = val;
    }
    __syncthreads();

    const int Lup = 2 * L;
#pragma unroll
    for (int q = 0; q < RC; q++) {
        int c = cb + q;
        float yl = __shfl_up_sync(0xffffffffu, v[q][7], 1);
        float yr = __shfl_down_sync(0xffffffffu, v[q][0], 1);
        if (lane == 0)  yl = (wic == 0)       ? YsE[2 * c]     : BndA3[c * WPC + wic - 1];
        if (lane == 31) yr = (wic == WPC - 1) ? YsE[2 * c + 1] : BndA0[c * WPC + wic + 1];
        float o[16];
        o[0] = 0.25f * yl + 0.75f * v[q][0];
#pragma unroll
        for (int j = 1; j < 8; j++) o[2 * j] = 0.25f * v[q][j - 1] + 0.75f * v[q][j];
#pragma unroll
        for (int j = 0; j < 7; j++) o[2 * j + 1] = 0.75f * v[q][j] + 0.25f * v[q][j + 1];
        o[15] = 0.75f * v[q][7] + 0.25f * yr;
        size_t off = ((size_t)b * COUT + c) * Lup + 2 * (tile * TL + lb);
#pragma unroll
        for (int i = 0; i < 4; i++)
            *(float4*)(y + off + 4 * i) =
                make_float4(o[4 * i], o[4 * i + 1], o[4 * i + 2], o[4 * i + 3]);
    }
}

// ---------------------------------------------------------------------------
// Narrow conv (L3/L4): R9-proven RC x4 config.
// ---------------------------------------------------------------------------
template<int CIN, int COUT, int DIL, int TL, int RC, int CHUNK, bool BN, bool FINAL>
__global__ __launch_bounds__(256, 3)
void conv_layer(const float* __restrict__ x, const float* __restrict__ wp,
                const float* __restrict__ gg, const float* __restrict__ bb,
                const float* __restrict__ mm, const float* __restrict__ vv,
                const float* __restrict__ bout, float* __restrict__ y, int L)
{
    constexpr int PAD   = 2 * DIL;
    constexpr int SFT   = PAD + 4;
    constexpr int HALO  = TL + 2 * PAD + 5;
    constexpr int HALOP = (HALO + 3) & ~3;
    constexpr int NPG   = TL / 4;
    constexpr int COUTP = (COUT + 3) & ~3;
    constexpr int NQ    = (RC + 1) / 2;
    constexpr int WCH   = CHUNK * 10 * COUTP;
    constexpr int NCH   = CIN / CHUNK;
    constexpr int WPC   = NPG / 32;

    const int tid  = threadIdx.x;
    const int tile = blockIdx.x;
    const int b    = blockIdx.y;
    const int pg   = tid % NPG;
    const int cg   = tid / NPG;
    const int lane = tid & 31;
    const int wic  = pg >> 5;
    const int lb   = pg * 4;
    const int cb   = cg * RC;

    extern __shared__ float sm[];
    float* Xbuf[2] = { sm, sm + CHUNK * HALOP };
    float* Wbuf[2] = { sm + 2 * CHUNK * HALOP, sm + 2 * CHUNK * HALOP + WCH };
    float* YsE   = sm + 2 * CHUNK * HALOP + 2 * WCH;
    float* BndA3 = YsE + 2 * COUT;
    float* BndA0 = BndA3 + COUT * WPC;

    const float* xb    = x + (size_t)b * CIN * L;
    const int    gbase = tile * TL - SFT;

    u64 acc[RC][2];
#pragma unroll
    for (int q = 0; q < RC; q++) { acc[q][0] = 0ull; acc[q][1] = 0ull; }

    float eacc = 0.f;
    const int eIdx = tid >> 1, eSide = tid & 1;
    int ej = 0;
    if (tid < 2 * COUT) {
        int gl = tile * TL + (eSide ? TL : -1);
        if (gl < 0)  gl = 0;
        if (gl >= L) gl = L - 1;
        ej = gl - tile * TL;
    }

    auto stage = [&](int p, int cc) {
        stage_x<CHUNK, HALO, HALOP, 4>(Xbuf[p], xb, L, cc, gbase, L, tid);
        const float4* wsrc = (const float4*)(wp + (size_t)cc * WCH);
        float* Wd = Wbuf[p];
        for (int idx = tid; idx < WCH / 4; idx += 256) {
            unsigned d = sm_u32(Wd + idx * 4);
            asm volatile("cp.async.cg.shared.global [%0], [%1], 16;"
                         :: "r"(d), "l"(wsrc + idx));
        }
        asm volatile("cp.async.commit_group;");
    };

    stage(0, 0);

    for (int cc = 0; cc < NCH; cc++) {
        const int p = cc & 1;
        asm volatile("cp.async.wait_group 0;");
        __syncthreads();
        if (cc + 1 < NCH) stage(p ^ 1, cc + 1);

        const float* Xs = Xbuf[p];
        const float* Ws = Wbuf[p];

#pragma unroll 2
        for (int ci = 0; ci < CHUNK; ci++) {
            const float* xr = Xs + ci * HALOP + lb + 4;
#pragma unroll
            for (int k = 0; k < 5; k++) {
                ulonglong2 xv = *(const ulonglong2*)(xr + k * DIL);
                u64 xp0 = xv.x, xp1 = xv.y;
                const float* wr = Ws + (ci * 5 + k) * 2 * COUTP + 2 * cb;
#pragma unroll
                for (int qq = 0; qq < NQ; qq++) {
                    ulonglong2 wv = *(const ulonglong2*)(wr + 4 * qq);
                    fma2(acc[2 * qq][0], wv.x, xp0);
                    fma2(acc[2 * qq][1], wv.x, xp1);
                    if (2 * qq + 1 < RC) {
                        fma2(acc[2 * qq + 1][0], wv.y, xp0);
                        fma2(acc[2 * qq + 1][1], wv.y, xp1);
                    }
                }
            }
        }

        if (tid < 2 * COUT) {
#pragma unroll 1
            for (int ci = 0; ci < CHUNK; ci++)
#pragma unroll
                for (int k = 0; k < 5; k++)
                    eacc = fmaf(Ws[(ci * 5 + k) * 2 * COUTP + 2 * eIdx],
                                Xs[ci * HALOP + ej + 4 + k * DIL], eacc);
        }
    }

    float v[RC][4];
#pragma unroll
    for (int q = 0; q < RC; q++) {
        int c = cb + q;
        float sc, sh;
        if (FINAL) { sc = 1.f; sh = bout[c]; }
        else {
            float inv = gg[c] * rsqrtf(vv[c] + 1e-5f);
            sc = inv; sh = bb[c] - mm[c] * inv;
        }
        float a0, a1, a2, a3;
        unpack2(acc[q][0], a0, a1);
        unpack2(acc[q][1], a2, a3);
        a0 = a0 * sc + sh; a1 = a1 * sc + sh;
        a2 = a2 * sc + sh; a3 = a3 * sc + sh;
        if (BN) {
            a0 = fmaxf(a0, 0.f); a1 = fmaxf(a1, 0.f);
            a2 = fmaxf(a2, 0.f); a3 = fmaxf(a3, 0.f);
        }
        v[q][0] = a0; v[q][1] = a1; v[q][2] = a2; v[q][3] = a3;
        if (lane == 31) BndA3[c * WPC + wic] = a3;
        if (lane == 0)  BndA0[c * WPC + wic] = a0;
    }
    if (tid < 2 * COUT) {
        int c = eIdx;
        float sc, sh;
        if (FINAL) { sc = 1.f; sh = bout[c]; }
        else {
            float inv = gg[c] * rsqrtf(vv[c] + 1e-5f);
            sc = inv; sh = bb[c] - mm[c] * inv;
        }
        float val = eacc * sc + sh;
        if (BN) val = fmaxf(val, 0.f);
        YsE[2 * c + eSide] = val;
    }
    __syncthreads();

    const int Lup = 2 * L;
#pragma unroll
    for (int q = 0; q < RC; q++) {
        int c = cb + q;
        float yl = __shfl_up_sync(0xffffffffu, v[q][3], 1);
        float yr = __shfl_down_sync(0xffffffffu, v[q][0], 1);
        if (lane == 0)  yl = (wic == 0)       ? YsE[2 * c]     : BndA3[c * WPC + wic - 1];
        if (lane == 31) yr = (wic == WPC - 1) ? YsE[2 * c + 1] : BndA0[c * WPC + wic + 1];
        float y0 = v[q][0], y1 = v[q][1], y2 = v[q][2], y3 = v[q][3];
        float o0 = 0.25f * yl + 0.75f * y0, o1 = 0.75f * y0 + 0.25f * y1;
        float o2 = 0.25f * y0 + 0.75f * y1, o3 = 0.75f * y1 + 0.25f * y2;
        float o4 = 0.25f * y1 + 0.75f * y2, o5 = 0.75f * y2 + 0.25f * y3;
        float o6 = 0.25f * y2 + 0.75f * y3, o7 = 0.75f * y3 + 0.25f * yr;
        size_t off = ((size_t)b * COUT + c) * Lup + 2 * (tile * TL + lb);
        *(float4*)(y + off)     = make_float4(o0, o1, o2, o3);
        *(float4*)(y + off + 4) = make_float4(o4, o5, o6, o7);
    }
}

// ---------------------------------------------------------------------------
#define TT 512
#define TTP 516
__global__ __launch_bounds__(256)
void transpose_loss(const float* __restrict__ in, const float* __restrict__ tg,
                    float* __restrict__ out, double* accum, int* mask)
{
    const int bt = blockIdx.y;
    const int t0 = blockIdx.x * TT;
    const int tid = threadIdx.x;
    extern __shared__ float tile[];

    for (int idx = tid; idx < 3 * 8 * TT; idx += 256) {
        int c = idx / (8 * TT), r = idx - c * (8 * TT);
        int st = r / TT, t = r - st * TT;
        tile[(c * 8 + st) * TTP + t] =
            in[((size_t)(bt * 8 + st) * 3 + c) * NT_OUT + t0 + t];
    }
    __syncthreads();

    float s = 0.f;
    bool nz = false;
    const size_t ob = ((size_t)bt * 3) * NT_OUT * 8 + (size_t)t0 * 8;
    const size_t cs = (size_t)NT_OUT * 8;
#pragma unroll 4
    for (int i = 0; i < (TT * 8) / 256; i++) {
        int f = i * 256 + tid;
        int t = f >> 3, st = f & 7;
        float o0 = tile[(0 * 8 + st) * TTP + t];
        float o1 = tile[(1 * 8 + st) * TTP + t];
        float o2 = tile[(2 * 8 + st) * TTP + t];
        out[ob + f]          = o0;
        out[ob + cs + f]     = o1;
        out[ob + 2 * cs + f] = o2;
        float t0v = tg[ob + f], t1v = tg[ob + cs + f], t2v = tg[ob + 2 * cs + f];
        float mx  = fmaxf(o0, fmaxf(o1, o2));
        float lse = mx + __logf(__expf(o0 - mx) + __expf(o1 - mx) + __expf(o2 - mx));
        s += t0v * (lse - o0) + t1v * (lse - o1) + t2v * (lse - o2);
        nz = nz || (t0v != 0.f) || (t1v != 0.f) || (t2v != 0.f);
    }
    if (nz) atomicOr(&mask[bt * 8 + (tid & 7)], 1);

    __shared__ float red[256];
    red[tid] = s;
    __syncthreads();
    for (int o = 128; o > 0; o >>= 1) {
        if (tid < o) red[tid] += red[tid + o];
        __syncthreads();
    }
    if (tid == 0) atomicAdd(accum, (double)red[0]);
}

__global__ void finalize_kernel(const double* accum, const int* mask,
                                float* out, int out_size)
{
    if (threadIdx.x != 0 || blockIdx.x != 0) return;
    int num = 0;
    for (int i = 0; i < BATCH; i++) num += (mask[i] ? 1 : 0);
    double loss = *accum / ((double)num * (double)NT_OUT);
    if ((unsigned)out_size > OUT_ELEMS) out[OUT_ELEMS] = (float)loss;
}

// ---------------------------------------------------------------------------
static constexpr int wide_smem(int CIN, int COUT, int DIL, int TL) {
    int halop = ((TL + 4 * DIL + 5) + 3) & ~3;
    int wpc = (TL / 8) / 32;
    return (2 * 8 * halop + 2 * 8 * 10 * COUT + 2 * COUT + 2 * COUT * wpc
            + 4 * COUT) * 4;
}
static constexpr int narrow_smem(int CIN, int COUT, int DIL, int TL) {
    int halop = ((TL + 4 * DIL + 5) + 3) & ~3;
    int coutp = (COUT + 3) & ~3;
    int wpc = (TL / 4) / 32;
    return (2 * 8 * halop + 2 * 8 * 10 * coutp + 2 * COUT + 2 * COUT * wpc) * 4;
}

extern "C" void kernel_launch(void* const* d_in, const int* in_sizes, int n_in,
                              void* d_out, int out_size)
{
    const float* x  = (const float*)d_in[0];
    const float* tg = (const float*)d_in[1];
    const float *w[5], *g[4], *bb[4], *mm[4], *vv[4], *b_out;

    bool inter = (n_in > 3) && (in_sizes[3] == 64);
    if (inter) {
        for (int i = 0; i < 4; i++) {
            w[i]  = (const float*)d_in[2 + 5 * i];
            g[i]  = (const float*)d_in[3 + 5 * i];
            bb[i] = (const float*)d_in[4 + 5 * i];
            mm[i] = (const float*)d_in[5 + 5 * i];
            vv[i] = (const float*)d_in[6 + 5 * i];
        }
    } else {
        for (int i = 0; i < 4; i++) {
            w[i]  = (const float*)d_in[2 + i];
            g[i]  = (const float*)d_in[6 + i];
            bb[i] = (const float*)d_in[10 + i];
            mm[i] = (const float*)d_in[14 + i];
            vv[i] = (const float*)d_in[18 + i];
        }
    }
    w[4]  = (const float*)d_in[22];
    b_out = (const float*)d_in[23];

    float *bufA, *bufB, *wprep;
    double* accum;
    int* mask;
    cudaGetSymbolAddress((void**)&bufA, g_bufA);
    cudaGetSymbolAddress((void**)&bufB, g_bufB);
    cudaGetSymbolAddress((void**)&wprep, g_wprep);
    cudaGetSymbolAddress((void**)&accum, g_loss_accum);
    cudaGetSymbolAddress((void**)&mask, g_mask);

    const size_t o0 = 0, o1 = 81920, o2 = 102400, o3 = 107520, o4 = 108800;

    constexpr int SM0 = wide_smem(128, 64, 1, 256);
    constexpr int SM1 = wide_smem(64, 32, 2, 512);
    constexpr int SM2 = wide_smem(32, 16, 4, 1024);
    constexpr int SM3 = narrow_smem(16, 8, 8, 1024);
    constexpr int SM4 = narrow_smem(8, 3, 16, 1024);
    constexpr int SMT = 3 * 8 * TTP * 4;

    cudaFuncSetAttribute(conv_wide<128, 64, 1, 256, true>,
                         cudaFuncAttributeMaxDynamicSharedMemorySize, SM0);
    cudaFuncSetAttribute(conv_wide<64, 32, 2, 512, true>,
                         cudaFuncAttributeMaxDynamicSharedMemorySize, SM1);
    cudaFuncSetAttribute(conv_wide<32, 16, 4, 1024, true>,
                         cudaFuncAttributeMaxDynamicSharedMemorySize, SM2);
    cudaFuncSetAttribute(conv_layer<16, 8, 8, 1024, 8, 8, true, false>,
                         cudaFuncAttributeMaxDynamicSharedMemorySize, SM3);
    cudaFuncSetAttribute(conv_layer<8, 3, 16, 1024, 3, 8, false, true>,
                         cudaFuncAttributeMaxDynamicSharedMemorySize, SM4);
    cudaFuncSetAttribute(transpose_loss,
                         cudaFuncAttributeMaxDynamicSharedMemorySize, SMT);

    prep_all<<<dim3(160, 6), 256>>>(w[0], w[1], w[2], w[3], w[4], wprep, accum, mask);

    conv_wide<128, 64, 1, 256, true>
        <<<dim3(1024 / 256, BATCH), 256, SM0>>>(x, wprep + o0, g[0], bb[0], mm[0], vv[0],
                                                bufA, 1024);
    conv_wide<64, 32, 2, 512, true>
        <<<dim3(2048 / 512, BATCH), 256, SM1>>>(bufA, wprep + o1, g[1], bb[1], mm[1], vv[1],
                                                bufB, 2048);
    conv_wide<32, 16, 4, 1024, true>
        <<<dim3(4096 / 1024, BATCH), 256, SM2>>>(bufB, wprep + o2, g[2], bb[2], mm[2], vv[2],
                                                 bufA, 4096);
    conv_layer<16, 8, 8, 1024, 8, 8, true, false>
        <<<dim3(8192 / 1024, BATCH), 256, SM3>>>(bufA, wprep + o3, g[3], bb[3], mm[3], vv[3],
                                                 nullptr, bufB, 8192);
    conv_layer<8, 3, 16, 1024, 3, 8, false, true>
        <<<dim3(16384 / 1024, BATCH), 256, SM4>>>(bufB, wprep + o4, nullptr, nullptr, nullptr,
                                                  nullptr, b_out, bufA, 16384);

    transpose_loss<<<dim3(NT_OUT / TT, 32), 256, SMT>>>(bufA, tg, (float*)d_out,
                                                        accum, mask);
    finalize_kernel<<<1, 1>>>(accum, mask, (float*)d_out, out_size);
}